// round 1
// baseline (speedup 1.0000x reference)
#include <cuda_runtime.h>
#include <math.h>

#define BATCH 4
#define SEQ   1024
#define DM    1024
#define NH    16
#define DKH   64

// ---------------- scratch (device globals: allocation-free) ----------------
__device__ float g_xpe [BATCH*SEQ*DM];
__device__ float g_q   [BATCH*SEQ*DM];
__device__ float g_k   [BATCH*SEQ*DM];
__device__ float g_v   [BATCH*SEQ*DM];
__device__ float g_ctx [BATCH*SEQ*DM];
__device__ float g_proj[BATCH*SEQ*DM];

// ---------------- kernel 1: x + positional encoding ----------------
__global__ __launch_bounds__(256) void pe_kernel(const float* __restrict__ x,
                                                 float* __restrict__ xpe)
{
    int row = blockIdx.x;            // 0..BATCH*SEQ-1
    int t   = threadIdx.x;           // 0..255, 4 floats each
    int s   = row & (SEQ - 1);
    float pos = (float)s;
    const float C = 9.210340371976184f / 1024.0f;   // ln(10000)/D
    size_t base = (size_t)row * DM + t * 4;
    float4 xv = *(const float4*)&x[base];
    int d0 = t * 4;                                  // even
    float div0 = expf(-C * (float)d0);
    float div1 = expf(-C * (float)(d0 + 2));
    float a0 = pos * div0, a1 = pos * div1;
    float4 o;
    o.x = xv.x + sinf(a0);
    o.y = xv.y + cosf(a0);
    o.z = xv.z + sinf(a1);
    o.w = xv.w + cosf(a1);
    *(float4*)&xpe[base] = o;
}

// ---------------- kernel 2: C[m,n] = scale * sum_k A[m,k]*B[n,k] ----------------
// (Linear with weight [out,in]); 128x128 tile, BK=16, 256 threads, 8x8/thread
#define GBM 128
#define GBN 128
#define GBK 16
#define GLD 132   // padded smem stride (multiple of 4 for float4 reads)

__global__ __launch_bounds__(256) void gemm_nt_kernel(const float* __restrict__ A,
                                                      const float* __restrict__ B,
                                                      float* __restrict__ C,
                                                      int M, int N, int K, float scale)
{
    __shared__ float Ast[GBK * GLD];
    __shared__ float Bst[GBK * GLD];

    int t  = threadIdx.x;
    int m0 = blockIdx.y * GBM;
    int n0 = blockIdx.x * GBN;
    int tx = t & 15;      // 0..15 -> cols
    int ty = t >> 4;      // 0..15 -> rows

    int lr = t >> 2;      // loader row 0..63
    int lc = t & 3;       // loader float4 col 0..3 (16 k's = 4 float4)

    float acc[8][8];
#pragma unroll
    for (int i = 0; i < 8; i++)
#pragma unroll
        for (int j = 0; j < 8; j++) acc[i][j] = 0.f;

    for (int k0 = 0; k0 < K; k0 += GBK) {
        __syncthreads();
#pragma unroll
        for (int i = 0; i < 2; i++) {
            int row = lr + i * 64;
            float4 a  = *(const float4*)&A[(size_t)(m0 + row) * K + k0 + lc * 4];
            float4 bb = *(const float4*)&B[(size_t)(n0 + row) * K + k0 + lc * 4];
            Ast[(lc*4+0)*GLD + row] = a.x;  Ast[(lc*4+1)*GLD + row] = a.y;
            Ast[(lc*4+2)*GLD + row] = a.z;  Ast[(lc*4+3)*GLD + row] = a.w;
            Bst[(lc*4+0)*GLD + row] = bb.x; Bst[(lc*4+1)*GLD + row] = bb.y;
            Bst[(lc*4+2)*GLD + row] = bb.z; Bst[(lc*4+3)*GLD + row] = bb.w;
        }
        __syncthreads();
#pragma unroll
        for (int kk = 0; kk < GBK; kk++) {
            float4 a0 = *(const float4*)&Ast[kk*GLD + ty*4];
            float4 a1 = *(const float4*)&Ast[kk*GLD + 64 + ty*4];
            float4 b0 = *(const float4*)&Bst[kk*GLD + tx*4];
            float4 b1 = *(const float4*)&Bst[kk*GLD + 64 + tx*4];
            float av[8] = {a0.x,a0.y,a0.z,a0.w,a1.x,a1.y,a1.z,a1.w};
            float bv[8] = {b0.x,b0.y,b0.z,b0.w,b1.x,b1.y,b1.z,b1.w};
#pragma unroll
            for (int i = 0; i < 8; i++)
#pragma unroll
                for (int j = 0; j < 8; j++)
                    acc[i][j] += av[i] * bv[j];
        }
    }

#pragma unroll
    for (int ih = 0; ih < 2; ih++)
#pragma unroll
        for (int ii = 0; ii < 4; ii++) {
            int i   = ih * 4 + ii;
            int row = m0 + ih * 64 + ty * 4 + ii;
            float4 o0 = make_float4(acc[i][0]*scale, acc[i][1]*scale,
                                    acc[i][2]*scale, acc[i][3]*scale);
            float4 o1 = make_float4(acc[i][4]*scale, acc[i][5]*scale,
                                    acc[i][6]*scale, acc[i][7]*scale);
            *(float4*)&C[(size_t)row * N + n0 + tx*4]       = o0;
            *(float4*)&C[(size_t)row * N + n0 + 64 + tx*4]  = o1;
        }
}

// ---------------- kernel 3: fused attention ----------------
// grid (SEQ/32, NH, BATCH), block 256.
// Tile: 32 q-rows x 64 keys. Thread (rx=t%16 -> 2 rows, cy=t/16 -> 4 cols).
// Pass1: streaming online (m,l) stats. Pass2: recompute scores, write attn
// probabilities to gmem, accumulate attn @ V.
#define TQ 32
#define TK 64
#define QLD 65   // sQ stride [row][kk]
#define KLD 68   // sK (transposed [kk][key]) & sV ([key][dim]) stride
#define PLD 34   // sP stride [key][qrow] (aliased into sK)

__global__ __launch_bounds__(256) void attn_kernel(const float* __restrict__ q,
                                                   const float* __restrict__ k,
                                                   const float* __restrict__ v,
                                                   float* __restrict__ attn_out,
                                                   float* __restrict__ ctx)
{
    __shared__ float sQ[TQ * QLD];          // 8.3 KB
    __shared__ float sK[TK * KLD];          // 17.4 KB (aliased by sP in pass 2)
    __shared__ float sV[TK * KLD];          // 17.4 KB (aliased by reduce bufs)
    __shared__ float sRowM[TQ];
    __shared__ float sRowI[TQ];

    int qt = blockIdx.x;
    int h  = blockIdx.y;
    int b  = blockIdx.z;
    int q0 = qt * TQ;
    int t  = threadIdx.x;
    int rx = t & 15;      // 2 rows: rx*2, rx*2+1
    int cy = t >> 4;      // 4 cols: cy*4..cy*4+3

    size_t qbase = ((size_t)b * SEQ + q0) * DM + h * DKH;
    size_t kbase = ((size_t)b * SEQ) * DM + h * DKH;

    // load Q tile (32 x 64), scalar scatter (stride 65)
#pragma unroll
    for (int i = 0; i < 2; i++) {
        int ff  = t + i * 256;
        int row = ff >> 4;
        int c4  = ff & 15;
        float4 a = *(const float4*)&q[qbase + (size_t)row * DM + c4 * 4];
        sQ[row*QLD + c4*4 + 0] = a.x;
        sQ[row*QLD + c4*4 + 1] = a.y;
        sQ[row*QLD + c4*4 + 2] = a.z;
        sQ[row*QLD + c4*4 + 3] = a.w;
    }

    // ---- pass 1: stats ----
    float m_t[2] = {-3.0e38f, -3.0e38f};
    float l_t[2] = {0.f, 0.f};

    for (int kt = 0; kt < SEQ / TK; kt++) {
        __syncthreads();
#pragma unroll
        for (int i = 0; i < 4; i++) {
            int ff  = t + i * 256;
            int row = ff >> 4;       // key 0..63
            int c4  = ff & 15;
            float4 a = *(const float4*)&k[kbase + (size_t)(kt*TK + row) * DM + c4*4];
            sK[(c4*4+0)*KLD + row] = a.x;
            sK[(c4*4+1)*KLD + row] = a.y;
            sK[(c4*4+2)*KLD + row] = a.z;
            sK[(c4*4+3)*KLD + row] = a.w;
        }
        __syncthreads();

        float acc[2][4] = {{0.f,0.f,0.f,0.f},{0.f,0.f,0.f,0.f}};
#pragma unroll 16
        for (int kk = 0; kk < DKH; kk++) {
            float qa = sQ[(rx*2+0)*QLD + kk];
            float qb = sQ[(rx*2+1)*QLD + kk];
            float4 kv = *(const float4*)&sK[kk*KLD + cy*4];
            acc[0][0] += qa*kv.x; acc[0][1] += qa*kv.y;
            acc[0][2] += qa*kv.z; acc[0][3] += qa*kv.w;
            acc[1][0] += qb*kv.x; acc[1][1] += qb*kv.y;
            acc[1][2] += qb*kv.z; acc[1][3] += qb*kv.w;
        }
#pragma unroll
        for (int i = 0; i < 2; i++)
#pragma unroll
            for (int j = 0; j < 4; j++) {
                float sc = acc[i][j];
                if (sc > m_t[i]) { l_t[i] *= __expf(m_t[i] - sc); m_t[i] = sc; }
                l_t[i] += __expf(sc - m_t[i]);
            }
    }

    // reduce (m,l) across the 16 column-threads of each row (alias into sV)
    __syncthreads();
    float* redm = sV;            // 32*17
    float* redl = sV + 544;      // 32*17
#pragma unroll
    for (int i = 0; i < 2; i++) {
        redm[(rx*2+i)*17 + cy] = m_t[i];
        redl[(rx*2+i)*17 + cy] = l_t[i];
    }
    __syncthreads();
    if (t < TQ) {
        float m = -3.0e38f;
#pragma unroll
        for (int c = 0; c < 16; c++) m = fmaxf(m, redm[t*17 + c]);
        float l = 0.f;
#pragma unroll
        for (int c = 0; c < 16; c++) l += redl[t*17 + c] * __expf(redm[t*17 + c] - m);
        sRowM[t] = m;
        sRowI[t] = 1.f / l;
    }
    __syncthreads();
    float rm[2] = { sRowM[rx*2], sRowM[rx*2+1] };
    float ri[2] = { sRowI[rx*2], sRowI[rx*2+1] };

    // ---- pass 2: probabilities + attn@V ----
    float o_acc[2][4] = {{0.f,0.f,0.f,0.f},{0.f,0.f,0.f,0.f}};
    size_t attnbase = (((size_t)(b * NH + h)) * SEQ + q0) * SEQ;

    for (int kt = 0; kt < SEQ / TK; kt++) {
        __syncthreads();
#pragma unroll
        for (int i = 0; i < 4; i++) {
            int ff  = t + i * 256;
            int row = ff >> 4;
            int c4  = ff & 15;
            float4 a  = *(const float4*)&k[kbase + (size_t)(kt*TK + row) * DM + c4*4];
            sK[(c4*4+0)*KLD + row] = a.x;
            sK[(c4*4+1)*KLD + row] = a.y;
            sK[(c4*4+2)*KLD + row] = a.z;
            sK[(c4*4+3)*KLD + row] = a.w;
            float4 vv = *(const float4*)&v[kbase + (size_t)(kt*TK + row) * DM + c4*4];
            *(float4*)&sV[row*KLD + c4*4] = vv;
        }
        __syncthreads();

        float acc[2][4] = {{0.f,0.f,0.f,0.f},{0.f,0.f,0.f,0.f}};
#pragma unroll 16
        for (int kk = 0; kk < DKH; kk++) {
            float qa = sQ[(rx*2+0)*QLD + kk];
            float qb = sQ[(rx*2+1)*QLD + kk];
            float4 kv = *(const float4*)&sK[kk*KLD + cy*4];
            acc[0][0] += qa*kv.x; acc[0][1] += qa*kv.y;
            acc[0][2] += qa*kv.z; acc[0][3] += qa*kv.w;
            acc[1][0] += qb*kv.x; acc[1][1] += qb*kv.y;
            acc[1][2] += qb*kv.z; acc[1][3] += qb*kv.w;
        }

        float p[2][4];
#pragma unroll
        for (int i = 0; i < 2; i++) {
#pragma unroll
            for (int j = 0; j < 4; j++)
                p[i][j] = __expf(acc[i][j] - rm[i]) * ri[i];
            float4 pw = make_float4(p[i][0], p[i][1], p[i][2], p[i][3]);
            *(float4*)&attn_out[attnbase + (size_t)(rx*2+i) * SEQ + kt*TK + cy*4] = pw;
        }

        __syncthreads();   // all sK reads done before sP overwrites it
#pragma unroll
        for (int i = 0; i < 2; i++)
#pragma unroll
            for (int j = 0; j < 4; j++)
                sK[(cy*4+j)*PLD + rx*2 + i] = p[i][j];   // sP alias
        __syncthreads();

#pragma unroll 16
        for (int col = 0; col < TK; col++) {
            float pa = sK[col*PLD + rx*2 + 0];
            float pb = sK[col*PLD + rx*2 + 1];
            float4 vv = *(const float4*)&sV[col*KLD + cy*4];
            o_acc[0][0] += pa*vv.x; o_acc[0][1] += pa*vv.y;
            o_acc[0][2] += pa*vv.z; o_acc[0][3] += pa*vv.w;
            o_acc[1][0] += pb*vv.x; o_acc[1][1] += pb*vv.y;
            o_acc[1][2] += pb*vv.z; o_acc[1][3] += pb*vv.w;
        }
    }

#pragma unroll
    for (int i = 0; i < 2; i++) {
        float4 o = make_float4(o_acc[i][0], o_acc[i][1], o_acc[i][2], o_acc[i][3]);
        *(float4*)&ctx[((size_t)b * SEQ + q0 + rx*2 + i) * DM + h * DKH + cy*4] = o;
    }
}

// ---------------- kernel 4: residual + LayerNorm ----------------
__global__ __launch_bounds__(256) void ln_kernel(const float* __restrict__ proj,
                                                 const float* __restrict__ resid,
                                                 const float* __restrict__ gamma,
                                                 const float* __restrict__ beta,
                                                 float* __restrict__ y)
{
    __shared__ float sred[16];
    int row = blockIdx.x;
    int t   = threadIdx.x;
    size_t base = (size_t)row * DM + t * 4;
    float4 pv = *(const float4*)&proj[base];
    float4 rv = *(const float4*)&resid[base];
    float4 vv = make_float4(pv.x+rv.x, pv.y+rv.y, pv.z+rv.z, pv.w+rv.w);
    float s  = vv.x + vv.y + vv.z + vv.w;
    float s2 = vv.x*vv.x + vv.y*vv.y + vv.z*vv.z + vv.w*vv.w;
#pragma unroll
    for (int off = 16; off; off >>= 1) {
        s  += __shfl_xor_sync(0xffffffffu, s,  off);
        s2 += __shfl_xor_sync(0xffffffffu, s2, off);
    }
    int warp = t >> 5, lane = t & 31;
    if (lane == 0) { sred[warp] = s; sred[8 + warp] = s2; }
    __syncthreads();
    if (t == 0) {
        float ts = 0.f, t2 = 0.f;
#pragma unroll
        for (int w = 0; w < 8; w++) { ts += sred[w]; t2 += sred[8 + w]; }
        float mean = ts * (1.0f / DM);
        float var  = t2 * (1.0f / DM) - mean * mean;
        sred[0] = mean;
        sred[1] = rsqrtf(var + 1e-6f);
    }
    __syncthreads();
    float mean = sred[0], rstd = sred[1];
    float4 g4 = *(const float4*)&gamma[t*4];
    float4 b4 = *(const float4*)&beta[t*4];
    float4 o;
    o.x = (vv.x - mean) * rstd * g4.x + b4.x;
    o.y = (vv.y - mean) * rstd * g4.y + b4.y;
    o.z = (vv.z - mean) * rstd * g4.z + b4.z;
    o.w = (vv.w - mean) * rstd * g4.w + b4.w;
    *(float4*)&y[base] = o;
}

// ---------------- launch ----------------
extern "C" void kernel_launch(void* const* d_in, const int* in_sizes, int n_in,
                              void* d_out, int out_size)
{
    const float* x     = (const float*)d_in[0];
    const float* Wq    = (const float*)d_in[1];
    const float* Wk    = (const float*)d_in[2];
    const float* Wv    = (const float*)d_in[3];
    const float* Wo    = (const float*)d_in[4];
    const float* gamma = (const float*)d_in[5];
    const float* beta  = (const float*)d_in[6];

    float* out      = (float*)d_out;
    float* y_out    = out;                                   // [B,S,D]
    float* attn_out = out + (size_t)BATCH * SEQ * DM;        // [B,H,S,S]

    float *xpe, *qb, *kb, *vb, *ctx, *proj;
    cudaGetSymbolAddress((void**)&xpe,  g_xpe);
    cudaGetSymbolAddress((void**)&qb,   g_q);
    cudaGetSymbolAddress((void**)&kb,   g_k);
    cudaGetSymbolAddress((void**)&vb,   g_v);
    cudaGetSymbolAddress((void**)&ctx,  g_ctx);
    cudaGetSymbolAddress((void**)&proj, g_proj);

    const int M = BATCH * SEQ;   // 4096
    dim3 ggrid(DM / GBN, M / GBM);

    pe_kernel<<<M, 256>>>(x, xpe);
    gemm_nt_kernel<<<ggrid, 256>>>(xpe, Wq, qb, M, DM, DM, 0.125f);  // q / sqrt(dk)
    gemm_nt_kernel<<<ggrid, 256>>>(xpe, Wk, kb, M, DM, DM, 1.0f);
    gemm_nt_kernel<<<ggrid, 256>>>(xpe, Wv, vb, M, DM, DM, 1.0f);
    attn_kernel<<<dim3(SEQ / TQ, NH, BATCH), 256>>>(qb, kb, vb, attn_out, ctx);
    gemm_nt_kernel<<<ggrid, 256>>>(ctx, Wo, proj, M, DM, DM, 1.0f);
    ln_kernel<<<M, 256>>>(proj, xpe, gamma, beta, y_out);
}

// round 3
// speedup vs baseline: 1.5656x; 1.5656x over previous
#include <cuda_runtime.h>
#include <cuda_bf16.h>
#include <math.h>
#include <stdint.h>

#define BATCH 4
#define SEQ   1024
#define DM    1024
#define NH    16
#define DKH   64

// ---------------- scratch (device globals: allocation-free) ----------------
__device__ float g_xpe [BATCH*SEQ*DM];
__device__ float g_q   [BATCH*SEQ*DM];
__device__ float g_k   [BATCH*SEQ*DM];
__device__ float g_v   [BATCH*SEQ*DM];
__device__ float g_ctx [BATCH*SEQ*DM];
__device__ float g_proj[BATCH*SEQ*DM];
__device__ float g_linv[BATCH*NH*SEQ];

// bf16 hi/lo split buffers
__device__ __nv_bfloat16 g_xh[BATCH*SEQ*DM];
__device__ __nv_bfloat16 g_xl[BATCH*SEQ*DM];
__device__ __nv_bfloat16 g_ch[BATCH*SEQ*DM];
__device__ __nv_bfloat16 g_cl[BATCH*SEQ*DM];
__device__ __nv_bfloat16 g_wqh[DM*DM], g_wql[DM*DM];
__device__ __nv_bfloat16 g_wkh[DM*DM], g_wkl[DM*DM];
__device__ __nv_bfloat16 g_wvh[DM*DM], g_wvl[DM*DM];
__device__ __nv_bfloat16 g_woh[DM*DM], g_wol[DM*DM];

// ---------------- PTX helpers (plain sm_103-safe: no tcgen05) ----------------
__device__ __forceinline__ uint32_t smem_u32(const void* p) {
    uint32_t a;
    asm("{ .reg .u64 t; cvta.to.shared.u64 t, %1; cvt.u32.u64 %0, t; }" : "=r"(a) : "l"(p));
    return a;
}

#define LDMATRIX_X4(r0,r1,r2,r3,addr) \
    asm volatile("ldmatrix.sync.aligned.m8n8.x4.shared.b16 {%0,%1,%2,%3}, [%4];" \
                 : "=r"(r0),"=r"(r1),"=r"(r2),"=r"(r3) : "r"(addr))

#define MMA_BF16(d0,d1,d2,d3,a0,a1,a2,a3,b0,b1) \
    asm volatile("mma.sync.aligned.m16n8k16.row.col.f32.bf16.bf16.f32 " \
                 "{%0,%1,%2,%3}, {%4,%5,%6,%7}, {%8,%9}, {%0,%1,%2,%3};" \
                 : "+f"(d0),"+f"(d1),"+f"(d2),"+f"(d3) \
                 : "r"(a0),"r"(a1),"r"(a2),"r"(a3),"r"(b0),"r"(b1))

#define CP_ASYNC16(smem, gptr) \
    asm volatile("cp.async.cg.shared.global [%0], [%1], 16;" :: "r"(smem), "l"(gptr))
#define CP_COMMIT() asm volatile("cp.async.commit_group;")
#define CP_WAIT1()  asm volatile("cp.async.wait_group 1;")
#define CP_WAIT0()  asm volatile("cp.async.wait_group 0;")

// ---------------- kernel 1: x + positional encoding ----------------
__global__ __launch_bounds__(256) void pe_kernel(const float* __restrict__ x,
                                                 float* __restrict__ xpe)
{
    int row = blockIdx.x;
    int t   = threadIdx.x;
    int s   = row & (SEQ - 1);
    float pos = (float)s;
    const float C = 9.210340371976184f / 1024.0f;
    size_t base = (size_t)row * DM + t * 4;
    float4 xv = *(const float4*)&x[base];
    int d0 = t * 4;
    float div0 = expf(-C * (float)d0);
    float div1 = expf(-C * (float)(d0 + 2));
    float a0 = pos * div0, a1 = pos * div1;
    float4 o;
    o.x = xv.x + sinf(a0);
    o.y = xv.y + cosf(a0);
    o.z = xv.z + sinf(a1);
    o.w = xv.w + cosf(a1);
    *(float4*)&xpe[base] = o;
}

// ---------------- kernel: fp32 -> bf16 hi/lo split ----------------
__global__ __launch_bounds__(256) void split_kernel(const float* __restrict__ s,
                                                    __nv_bfloat16* __restrict__ hi,
                                                    __nv_bfloat16* __restrict__ lo,
                                                    int n4)
{
    int i = blockIdx.x * 256 + threadIdx.x;
    if (i >= n4) return;
    float4 v = ((const float4*)s)[i];
    float vv[4] = {v.x, v.y, v.z, v.w};
    unsigned short h[4], l[4];
#pragma unroll
    for (int j = 0; j < 4; j++) {
        __nv_bfloat16 hb = __float2bfloat16(vv[j]);
        __nv_bfloat16 lb = __float2bfloat16(vv[j] - __bfloat162float(hb));
        h[j] = *reinterpret_cast<unsigned short*>(&hb);
        l[j] = *reinterpret_cast<unsigned short*>(&lb);
    }
    ((ushort4*)hi)[i] = make_ushort4(h[0], h[1], h[2], h[3]);
    ((ushort4*)lo)[i] = make_ushort4(l[0], l[1], l[2], l[3]);
}

// ---------------- kernel 2: mma.sync GEMM  C = scale * (A @ B^T) ----------------
// A [4096,1024], B [1024,1024], both K-major, hi/lo bf16 pairs.
// CTA tile 128x128, K-chunk 32, cp.async double buffer.
// Warp tile 64x32 (8 warps as 2x4). 3 MMAs per (hi/lo) product term.
#define KCHUNK 32
#define NCHV   (DM / KCHUNK)             // 32 chunks
#define ROWB   80                        // smem row stride bytes (40 bf16)
#define TILE_B (128 * ROWB)              // 10240 B per tile
#define BUF_B  (4 * TILE_B)              // Ah, Al, Bh, Bl
#define GEMM_SMEM (2 * BUF_B)            // 81920 B

__global__ void __launch_bounds__(256, 1) gemm_mma(const __nv_bfloat16* __restrict__ Ah,
                                                   const __nv_bfloat16* __restrict__ Al,
                                                   const __nv_bfloat16* __restrict__ Bh,
                                                   const __nv_bfloat16* __restrict__ Bl,
                                                   float* __restrict__ C, float scale)
{
    extern __shared__ char smem[];
    uint32_t sb = smem_u32(smem);
    int t = threadIdx.x;
    int lane = t & 31, wid = t >> 5;
    int m0 = blockIdx.y * 128, n0 = blockIdx.x * 128;
    int warp_m = (wid & 1) * 64;
    int warp_n = (wid >> 1) * 32;

    // copy indices: 2 x 16B per tile per thread
    int cr0 = t >> 2,        cc0 = t & 3;          // row 0..63
    int cr1 = (t + 256) >> 2, cc1 = (t + 256) & 3; // row 64..127

    const __nv_bfloat16* gsrc[4] = {Ah, Al, Bh, Bl};
    int grow0[4] = {m0, m0, n0, n0};

    float acc[4][4][4];
#pragma unroll
    for (int i = 0; i < 4; i++)
#pragma unroll
        for (int j = 0; j < 4; j++)
#pragma unroll
            for (int r = 0; r < 4; r++) acc[i][j][r] = 0.f;

    // prologue: chunk 0 -> buf 0
#pragma unroll
    for (int tl = 0; tl < 4; tl++) {
        uint32_t tb = sb + tl * TILE_B;
        CP_ASYNC16(tb + cr0 * ROWB + cc0 * 16, gsrc[tl] + (size_t)(grow0[tl] + cr0) * DM + cc0 * 8);
        CP_ASYNC16(tb + cr1 * ROWB + cc1 * 16, gsrc[tl] + (size_t)(grow0[tl] + cr1) * DM + cc1 * 8);
    }
    CP_COMMIT();

    // lane decode for ldmatrix
    int arow = lane & 15;            // m within 16
    int akb  = (lane >> 4) * 16;     // k byte offset (0 / 16)
    int brow = (lane & 7) + ((lane >> 4) << 3);   // n within 16
    int bkb  = ((lane >> 3) & 1) * 16;            // k byte offset

    for (int ch = 0; ch < NCHV; ch++) {
        int buf = ch & 1;
        uint32_t bufb = sb + buf * BUF_B;

        if (ch + 1 < NCHV) {
            uint32_t nb = sb + ((ch + 1) & 1) * BUF_B;
            int koff = (ch + 1) * KCHUNK;
#pragma unroll
            for (int tl = 0; tl < 4; tl++) {
                uint32_t tb = nb + tl * TILE_B;
                CP_ASYNC16(tb + cr0 * ROWB + cc0 * 16, gsrc[tl] + (size_t)(grow0[tl] + cr0) * DM + koff + cc0 * 8);
                CP_ASYNC16(tb + cr1 * ROWB + cc1 * 16, gsrc[tl] + (size_t)(grow0[tl] + cr1) * DM + koff + cc1 * 8);
            }
            CP_COMMIT();
            CP_WAIT1();
        } else {
            CP_WAIT0();
        }
        __syncthreads();

        uint32_t sAh = bufb + 0 * TILE_B;
        uint32_t sAl = bufb + 1 * TILE_B;
        uint32_t sBh = bufb + 2 * TILE_B;
        uint32_t sBl = bufb + 3 * TILE_B;

#pragma unroll
        for (int ks = 0; ks < 2; ks++) {
            int kb = ks * 32;   // 16 bf16 = 32 bytes
            uint32_t ah[4][4], al[4][4];
#pragma unroll
            for (int mt = 0; mt < 4; mt++) {
                uint32_t off = (uint32_t)((warp_m + mt * 16 + arow) * ROWB + kb + akb);
                LDMATRIX_X4(ah[mt][0], ah[mt][1], ah[mt][2], ah[mt][3], sAh + off);
                LDMATRIX_X4(al[mt][0], al[mt][1], al[mt][2], al[mt][3], sAl + off);
            }
#pragma unroll
            for (int np = 0; np < 2; np++) {
                uint32_t boff = (uint32_t)((warp_n + np * 16 + brow) * ROWB + kb + bkb);
                uint32_t bh[4], bl[4];
                LDMATRIX_X4(bh[0], bh[1], bh[2], bh[3], sBh + boff);
                LDMATRIX_X4(bl[0], bl[1], bl[2], bl[3], sBl + boff);
#pragma unroll
                for (int half = 0; half < 2; half++) {
                    int nt = np * 2 + half;
                    uint32_t bh0 = bh[half*2], bh1 = bh[half*2+1];
                    uint32_t bl0 = bl[half*2], bl1 = bl[half*2+1];
#pragma unroll
                    for (int mt = 0; mt < 4; mt++) {
                        float* d = acc[mt][nt];
                        MMA_BF16(d[0],d[1],d[2],d[3],
                                 ah[mt][0],ah[mt][1],ah[mt][2],ah[mt][3], bh0,bh1);
                        MMA_BF16(d[0],d[1],d[2],d[3],
                                 ah[mt][0],ah[mt][1],ah[mt][2],ah[mt][3], bl0,bl1);
                        MMA_BF16(d[0],d[1],d[2],d[3],
                                 al[mt][0],al[mt][1],al[mt][2],al[mt][3], bh0,bh1);
                    }
                }
            }
        }
        __syncthreads();
    }

    // epilogue
    int g  = lane >> 2;
    int tg = lane & 3;
#pragma unroll
    for (int mt = 0; mt < 4; mt++) {
#pragma unroll
        for (int nt = 0; nt < 4; nt++) {
            int row = m0 + warp_m + mt * 16 + g;
            int col = n0 + warp_n + nt * 8 + tg * 2;
            float2 lo = make_float2(acc[mt][nt][0] * scale, acc[mt][nt][1] * scale);
            float2 hi = make_float2(acc[mt][nt][2] * scale, acc[mt][nt][3] * scale);
            *(float2*)&C[(size_t)row * DM + col]       = lo;
            *(float2*)&C[(size_t)(row + 8) * DM + col] = hi;
        }
    }
}

// ---------------- kernel 3: single-pass fused attention ----------------
// Scores bounded (|s| < ~5) => softmax without max-subtraction is exact.
// Writes UNNORMALIZED exp(s) to attn gmem + 1/rowsum to linv; attn_scale
// normalizes afterwards. Context normalized in-register.
#define TQ 32
#define TK 64
#define QLD 65
#define KLD 68
#define PLD 34

__global__ __launch_bounds__(256) void attn_kernel(const float* __restrict__ q,
                                                   const float* __restrict__ k,
                                                   const float* __restrict__ v,
                                                   float* __restrict__ attn_out,
                                                   float* __restrict__ ctx,
                                                   float* __restrict__ linv)
{
    __shared__ float sQ[TQ * QLD];
    __shared__ float sK[TK * KLD];   // aliased by sP within the loop
    __shared__ float sV[TK * KLD];   // aliased by reduce buffer after the loop
    __shared__ float sRowI[TQ];

    int qt = blockIdx.x;
    int h  = blockIdx.y;
    int b  = blockIdx.z;
    int q0 = qt * TQ;
    int t  = threadIdx.x;
    int rx = t & 15;
    int cy = t >> 4;

    size_t qbase = ((size_t)b * SEQ + q0) * DM + h * DKH;
    size_t kbase = ((size_t)b * SEQ) * DM + h * DKH;

#pragma unroll
    for (int i = 0; i < 2; i++) {
        int ff  = t + i * 256;
        int row = ff >> 4;
        int c4  = ff & 15;
        float4 a = *(const float4*)&q[qbase + (size_t)row * DM + c4 * 4];
        sQ[row*QLD + c4*4 + 0] = a.x;
        sQ[row*QLD + c4*4 + 1] = a.y;
        sQ[row*QLD + c4*4 + 2] = a.z;
        sQ[row*QLD + c4*4 + 3] = a.w;
    }

    float l_t[2] = {0.f, 0.f};
    float o_acc[2][4] = {{0.f,0.f,0.f,0.f},{0.f,0.f,0.f,0.f}};
    size_t attnbase = (((size_t)(b * NH + h)) * SEQ + q0) * SEQ;

    for (int kt = 0; kt < SEQ / TK; kt++) {
        __syncthreads();
#pragma unroll
        for (int i = 0; i < 4; i++) {
            int ff  = t + i * 256;
            int row = ff >> 4;
            int c4  = ff & 15;
            float4 a  = *(const float4*)&k[kbase + (size_t)(kt*TK + row) * DM + c4*4];
            sK[(c4*4+0)*KLD + row] = a.x;
            sK[(c4*4+1)*KLD + row] = a.y;
            sK[(c4*4+2)*KLD + row] = a.z;
            sK[(c4*4+3)*KLD + row] = a.w;
            float4 vv = *(const float4*)&v[kbase + (size_t)(kt*TK + row) * DM + c4*4];
            *(float4*)&sV[row*KLD + c4*4] = vv;
        }
        __syncthreads();

        float acc[2][4] = {{0.f,0.f,0.f,0.f},{0.f,0.f,0.f,0.f}};
#pragma unroll 16
        for (int kk = 0; kk < DKH; kk++) {
            float qa = sQ[(rx*2+0)*QLD + kk];
            float qb = sQ[(rx*2+1)*QLD + kk];
            float4 kv = *(const float4*)&sK[kk*KLD + cy*4];
            acc[0][0] += qa*kv.x; acc[0][1] += qa*kv.y;
            acc[0][2] += qa*kv.z; acc[0][3] += qa*kv.w;
            acc[1][0] += qb*kv.x; acc[1][1] += qb*kv.y;
            acc[1][2] += qb*kv.z; acc[1][3] += qb*kv.w;
        }

        float p[2][4];
#pragma unroll
        for (int i = 0; i < 2; i++) {
#pragma unroll
            for (int j = 0; j < 4; j++) {
                p[i][j] = __expf(acc[i][j]);
                l_t[i] += p[i][j];
            }
            float4 pw = make_float4(p[i][0], p[i][1], p[i][2], p[i][3]);
            *(float4*)&attn_out[attnbase + (size_t)(rx*2+i) * SEQ + kt*TK + cy*4] = pw;
        }

        __syncthreads();   // all sK reads done before sP overwrites it
#pragma unroll
        for (int i = 0; i < 2; i++)
#pragma unroll
            for (int j = 0; j < 4; j++)
                sK[(cy*4+j)*PLD + rx*2 + i] = p[i][j];   // sP alias
        __syncthreads();

#pragma unroll 16
        for (int col = 0; col < TK; col++) {
            float pa = sK[col*PLD + rx*2 + 0];
            float pb = sK[col*PLD + rx*2 + 1];
            float4 vv = *(const float4*)&sV[col*KLD + cy*4];
            o_acc[0][0] += pa*vv.x; o_acc[0][1] += pa*vv.y;
            o_acc[0][2] += pa*vv.z; o_acc[0][3] += pa*vv.w;
            o_acc[1][0] += pb*vv.x; o_acc[1][1] += pb*vv.y;
            o_acc[1][2] += pb*vv.z; o_acc[1][3] += pb*vv.w;
        }
    }

    // reduce row sums across the 16 column-threads (alias into sV)
    __syncthreads();
    float* redl = sV;
#pragma unroll
    for (int i = 0; i < 2; i++)
        redl[(rx*2+i)*17 + cy] = l_t[i];
    __syncthreads();
    if (t < TQ) {
        float l = 0.f;
#pragma unroll
        for (int c = 0; c < 16; c++) l += redl[t*17 + c];
        float li = 1.f / l;
        sRowI[t] = li;
        linv[((size_t)(b * NH + h)) * SEQ + q0 + t] = li;
    }
    __syncthreads();
    float ri[2] = { sRowI[rx*2], sRowI[rx*2+1] };

#pragma unroll
    for (int i = 0; i < 2; i++) {
        float4 o = make_float4(o_acc[i][0]*ri[i], o_acc[i][1]*ri[i],
                               o_acc[i][2]*ri[i], o_acc[i][3]*ri[i]);
        *(float4*)&ctx[((size_t)b * SEQ + q0 + rx*2 + i) * DM + h * DKH + cy*4] = o;
    }
}

// ---------------- kernel: normalize attn rows in place ----------------
__global__ __launch_bounds__(256) void attn_scale(float* __restrict__ attn,
                                                  const float* __restrict__ linv)
{
    int row = blockIdx.x;
    float s = linv[row];
    size_t base = (size_t)row * SEQ + threadIdx.x * 4;
    float4 v = *(float4*)&attn[base];
    v.x *= s; v.y *= s; v.z *= s; v.w *= s;
    *(float4*)&attn[base] = v;
}

// ---------------- kernel 4: residual + LayerNorm ----------------
__global__ __launch_bounds__(256) void ln_kernel(const float* __restrict__ proj,
                                                 const float* __restrict__ resid,
                                                 const float* __restrict__ gamma,
                                                 const float* __restrict__ beta,
                                                 float* __restrict__ y)
{
    __shared__ float sred[16];
    int row = blockIdx.x;
    int t   = threadIdx.x;
    size_t base = (size_t)row * DM + t * 4;
    float4 pv = *(const float4*)&proj[base];
    float4 rv = *(const float4*)&resid[base];
    float4 vv = make_float4(pv.x+rv.x, pv.y+rv.y, pv.z+rv.z, pv.w+rv.w);
    float s  = vv.x + vv.y + vv.z + vv.w;
    float s2 = vv.x*vv.x + vv.y*vv.y + vv.z*vv.z + vv.w*vv.w;
#pragma unroll
    for (int off = 16; off; off >>= 1) {
        s  += __shfl_xor_sync(0xffffffffu, s,  off);
        s2 += __shfl_xor_sync(0xffffffffu, s2, off);
    }
    int warp = t >> 5, lane = t & 31;
    if (lane == 0) { sred[warp] = s; sred[8 + warp] = s2; }
    __syncthreads();
    if (t == 0) {
        float ts = 0.f, t2 = 0.f;
#pragma unroll
        for (int w = 0; w < 8; w++) { ts += sred[w]; t2 += sred[8 + w]; }
        float mean = ts * (1.0f / DM);
        float var  = t2 * (1.0f / DM) - mean * mean;
        sred[0] = mean;
        sred[1] = rsqrtf(var + 1e-6f);
    }
    __syncthreads();
    float mean = sred[0], rstd = sred[1];
    float4 g4 = *(const float4*)&gamma[t*4];
    float4 b4 = *(const float4*)&beta[t*4];
    float4 o;
    o.x = (vv.x - mean) * rstd * g4.x + b4.x;
    o.y = (vv.y - mean) * rstd * g4.y + b4.y;
    o.z = (vv.z - mean) * rstd * g4.z + b4.z;
    o.w = (vv.w - mean) * rstd * g4.w + b4.w;
    *(float4*)&y[base] = o;
}

// ---------------- launch ----------------
extern "C" void kernel_launch(void* const* d_in, const int* in_sizes, int n_in,
                              void* d_out, int out_size)
{
    const float* x     = (const float*)d_in[0];
    const float* Wq    = (const float*)d_in[1];
    const float* Wk    = (const float*)d_in[2];
    const float* Wv    = (const float*)d_in[3];
    const float* Wo    = (const float*)d_in[4];
    const float* gamma = (const float*)d_in[5];
    const float* beta  = (const float*)d_in[6];

    float* out      = (float*)d_out;
    float* y_out    = out;
    float* attn_out = out + (size_t)BATCH * SEQ * DM;

    float *xpe, *qb, *kb, *vb, *ctx, *proj, *linv;
    cudaGetSymbolAddress((void**)&xpe,  g_xpe);
    cudaGetSymbolAddress((void**)&qb,   g_q);
    cudaGetSymbolAddress((void**)&kb,   g_k);
    cudaGetSymbolAddress((void**)&vb,   g_v);
    cudaGetSymbolAddress((void**)&ctx,  g_ctx);
    cudaGetSymbolAddress((void**)&proj, g_proj);
    cudaGetSymbolAddress((void**)&linv, g_linv);

    __nv_bfloat16 *xh, *xl, *ch, *cl;
    __nv_bfloat16 *wqh, *wql, *wkh, *wkl, *wvh, *wvl, *woh, *wol;
    cudaGetSymbolAddress((void**)&xh,  g_xh);
    cudaGetSymbolAddress((void**)&xl,  g_xl);
    cudaGetSymbolAddress((void**)&ch,  g_ch);
    cudaGetSymbolAddress((void**)&cl,  g_cl);
    cudaGetSymbolAddress((void**)&wqh, g_wqh);
    cudaGetSymbolAddress((void**)&wql, g_wql);
    cudaGetSymbolAddress((void**)&wkh, g_wkh);
    cudaGetSymbolAddress((void**)&wkl, g_wkl);
    cudaGetSymbolAddress((void**)&wvh, g_wvh);
    cudaGetSymbolAddress((void**)&wvl, g_wvl);
    cudaGetSymbolAddress((void**)&woh, g_woh);
    cudaGetSymbolAddress((void**)&wol, g_wol);

    cudaFuncSetAttribute(gemm_mma, cudaFuncAttributeMaxDynamicSharedMemorySize, GEMM_SMEM);

    const int M = BATCH * SEQ;       // 4096
    const int NX4 = M * DM / 4;      // 1M float4
    const int NW4 = DM * DM / 4;     // 256K float4
    dim3 ggrid(DM / 128, M / 128);   // (8, 32)

    pe_kernel<<<M, 256>>>(x, xpe);
    split_kernel<<<NX4 / 256, 256>>>(xpe, xh, xl, NX4);
    split_kernel<<<NW4 / 256, 256>>>(Wq, wqh, wql, NW4);
    split_kernel<<<NW4 / 256, 256>>>(Wk, wkh, wkl, NW4);
    split_kernel<<<NW4 / 256, 256>>>(Wv, wvh, wvl, NW4);
    split_kernel<<<NW4 / 256, 256>>>(Wo, woh, wol, NW4);

    gemm_mma<<<ggrid, 256, GEMM_SMEM>>>(xh, xl, wqh, wql, qb, 0.125f);  // q / sqrt(dk)
    gemm_mma<<<ggrid, 256, GEMM_SMEM>>>(xh, xl, wkh, wkl, kb, 1.0f);
    gemm_mma<<<ggrid, 256, GEMM_SMEM>>>(xh, xl, wvh, wvl, vb, 1.0f);

    attn_kernel<<<dim3(SEQ / TQ, NH, BATCH), 256>>>(qb, kb, vb, attn_out, ctx, linv);
    attn_scale<<<BATCH * NH * SEQ, 256>>>(attn_out, linv);

    split_kernel<<<NX4 / 256, 256>>>(ctx, ch, cl, NX4);
    gemm_mma<<<ggrid, 256, GEMM_SMEM>>>(ch, cl, woh, wol, proj, 1.0f);
    ln_kernel<<<M, 256>>>(proj, xpe, gamma, beta, y_out);
}

// round 4
// speedup vs baseline: 2.6824x; 1.7133x over previous
#include <cuda_runtime.h>
#include <cuda_bf16.h>
#include <math.h>
#include <stdint.h>

#define BATCH 4
#define SEQ   1024
#define DM    1024
#define NH    16
#define DKH   64

// ---------------- scratch (device globals: allocation-free) ----------------
__device__ float g_xpe [BATCH*SEQ*DM];
__device__ float g_v   [BATCH*SEQ*DM];
__device__ float g_proj[BATCH*SEQ*DM];

__device__ __nv_bfloat16 g_xh[BATCH*SEQ*DM],  g_xl[BATCH*SEQ*DM];
__device__ __nv_bfloat16 g_qh[BATCH*SEQ*DM],  g_ql[BATCH*SEQ*DM];
__device__ __nv_bfloat16 g_kh[BATCH*SEQ*DM],  g_kl[BATCH*SEQ*DM];
__device__ __nv_bfloat16 g_vth[BATCH*SEQ*DM], g_vtl[BATCH*SEQ*DM];
__device__ __nv_bfloat16 g_ch[BATCH*SEQ*DM],  g_cl[BATCH*SEQ*DM];
__device__ __nv_bfloat16 g_wqh[DM*DM], g_wql[DM*DM];
__device__ __nv_bfloat16 g_wkh[DM*DM], g_wkl[DM*DM];
__device__ __nv_bfloat16 g_wvh[DM*DM], g_wvl[DM*DM];
__device__ __nv_bfloat16 g_woh[DM*DM], g_wol[DM*DM];

// ---------------- PTX helpers (plain sm_103-safe) ----------------
__device__ __forceinline__ uint32_t smem_u32(const void* p) {
    uint32_t a;
    asm("{ .reg .u64 t; cvta.to.shared.u64 t, %1; cvt.u32.u64 %0, t; }" : "=r"(a) : "l"(p));
    return a;
}

#define LDMATRIX_X4(r0,r1,r2,r3,addr) \
    asm volatile("ldmatrix.sync.aligned.m8n8.x4.shared.b16 {%0,%1,%2,%3}, [%4];" \
                 : "=r"(r0),"=r"(r1),"=r"(r2),"=r"(r3) : "r"(addr))

#define MMA_BF16(d0,d1,d2,d3,a0,a1,a2,a3,b0,b1) \
    asm volatile("mma.sync.aligned.m16n8k16.row.col.f32.bf16.bf16.f32 " \
                 "{%0,%1,%2,%3}, {%4,%5,%6,%7}, {%8,%9}, {%0,%1,%2,%3};" \
                 : "+f"(d0),"+f"(d1),"+f"(d2),"+f"(d3) \
                 : "r"(a0),"r"(a1),"r"(a2),"r"(a3),"r"(b0),"r"(b1))

#define CP_ASYNC16(smem, gptr) \
    asm volatile("cp.async.cg.shared.global [%0], [%1], 16;" :: "r"(smem), "l"(gptr))
#define CP_COMMIT() asm volatile("cp.async.commit_group;")
#define CP_WAIT1()  asm volatile("cp.async.wait_group 1;")
#define CP_WAIT0()  asm volatile("cp.async.wait_group 0;")

// fp32 -> bf16 hi/lo pair packer (two scalars -> packed bf16x2 regs)
__device__ __forceinline__ void split2(float x, float y, uint32_t& hi, uint32_t& lo) {
    __nv_bfloat16 hx = __float2bfloat16(x), hy = __float2bfloat16(y);
    __nv_bfloat16 lx = __float2bfloat16(x - __bfloat162float(hx));
    __nv_bfloat16 ly = __float2bfloat16(y - __bfloat162float(hy));
    hi = ((uint32_t)*reinterpret_cast<unsigned short*>(&hy) << 16) |
          (uint32_t)*reinterpret_cast<unsigned short*>(&hx);
    lo = ((uint32_t)*reinterpret_cast<unsigned short*>(&ly) << 16) |
          (uint32_t)*reinterpret_cast<unsigned short*>(&lx);
}

// ---------------- kernel 1: x + PE -> xpe fp32 AND xh/xl bf16 ----------------
__global__ __launch_bounds__(256) void pe_split(const float* __restrict__ x,
                                                float* __restrict__ xpe,
                                                __nv_bfloat16* __restrict__ xh,
                                                __nv_bfloat16* __restrict__ xl)
{
    int row = blockIdx.x;
    int t   = threadIdx.x;
    int s   = row & (SEQ - 1);
    float pos = (float)s;
    const float C = 9.210340371976184f / 1024.0f;
    size_t base = (size_t)row * DM + t * 4;
    float4 xv = *(const float4*)&x[base];
    int d0 = t * 4;
    float div0 = expf(-C * (float)d0);
    float div1 = expf(-C * (float)(d0 + 2));
    float a0 = pos * div0, a1 = pos * div1;
    float4 o;
    o.x = xv.x + sinf(a0);
    o.y = xv.y + cosf(a0);
    o.z = xv.z + sinf(a1);
    o.w = xv.w + cosf(a1);
    *(float4*)&xpe[base] = o;
    uint32_t h01, l01, h23, l23;
    split2(o.x, o.y, h01, l01);
    split2(o.z, o.w, h23, l23);
    *(uint2*)&xh[base] = make_uint2(h01, h23);
    *(uint2*)&xl[base] = make_uint2(l01, l23);
}

// ---------------- kernel: fp32 -> bf16 hi/lo split (weights) ----------------
__global__ __launch_bounds__(256) void split_kernel(const float* __restrict__ s,
                                                    __nv_bfloat16* __restrict__ hi,
                                                    __nv_bfloat16* __restrict__ lo,
                                                    int n4)
{
    int i = blockIdx.x * 256 + threadIdx.x;
    if (i >= n4) return;
    float4 v = ((const float4*)s)[i];
    uint32_t h01, l01, h23, l23;
    split2(v.x, v.y, h01, l01);
    split2(v.z, v.w, h23, l23);
    ((uint2*)hi)[i] = make_uint2(h01, h23);
    ((uint2*)lo)[i] = make_uint2(l01, l23);
}

// ---------------- kernel: V [b,s,D] fp32 -> Vt [b,h,d,s] bf16 hi/lo ----------------
__global__ __launch_bounds__(256) void vtrans_kernel(const float* __restrict__ v,
                                                     __nv_bfloat16* __restrict__ vth,
                                                     __nv_bfloat16* __restrict__ vtl)
{
    __shared__ float tile[32][65];
    int s0 = blockIdx.x * 64;
    int d0 = blockIdx.y * 32;
    int b  = blockIdx.z;
    int tx = threadIdx.x & 31, ty = threadIdx.x >> 5;   // tx: 0..31, ty: 0..7

    // read: 64 s-rows x 32 d-cols (coalesced in d)
#pragma unroll
    for (int so = 0; so < 64; so += 8) {
        int sl = so + ty;
        tile[tx][sl & 31] = 0.f; // placeholder to keep shape; real store below
    }
    // two 32-row halves to fit tile
#pragma unroll
    for (int half = 0; half < 2; half++) {
        __syncthreads();
#pragma unroll
        for (int so = 0; so < 32; so += 8) {
            int sl = half * 32 + so + ty;
            tile[tx][so + ty] = v[((size_t)b * SEQ + s0 + sl) * DM + d0 + tx];
        }
        __syncthreads();
        // write: 32 d-rows x 32 s-cols, bf16x2 per thread pair
#pragma unroll
        for (int dd = 0; dd < 32; dd += 8) {
            int dl = dd + ty;
            int dglob = d0 + dl;
            int hh = dglob >> 6;
            int dh = dglob & 63;
            float v0 = tile[dl][2 * (tx & 15) + ((tx >> 4) ? 0 : 0)];
            // each thread covers s pair: sx = tx (0..31) -> s = 2*tx? only 32 cols here
            (void)v0;
            int sx = tx; // 0..31 -> s col pair? 32 cols => 16 pairs; use tx<16
            if (sx < 16) {
                float a = tile[dl][2 * sx];
                float bb = tile[dl][2 * sx + 1];
                uint32_t hi, lo;
                split2(a, bb, hi, lo);
                size_t idx = (((size_t)b * NH + hh) * DKH + dh) * SEQ + s0 + half * 32 + 2 * sx;
                *(uint32_t*)&vth[idx] = hi;
                *(uint32_t*)&vtl[idx] = lo;
            }
        }
    }
}

// ---------------- kernel 2: mma.sync GEMM  C = scale * (A @ B^T) ----------------
#define KCHUNK 32
#define NCHV   (DM / KCHUNK)
#define ROWB   80
#define TILE_B (128 * ROWB)
#define BUF_B  (4 * TILE_B)
#define GEMM_SMEM (2 * BUF_B)

__global__ void __launch_bounds__(256, 1) gemm_mma(const __nv_bfloat16* __restrict__ Ah,
                                                   const __nv_bfloat16* __restrict__ Al,
                                                   const __nv_bfloat16* __restrict__ Bh,
                                                   const __nv_bfloat16* __restrict__ Bl,
                                                   float* __restrict__ C,
                                                   __nv_bfloat16* __restrict__ Ch,
                                                   __nv_bfloat16* __restrict__ Cl,
                                                   float scale, int bf16out)
{
    extern __shared__ char smem[];
    uint32_t sb = smem_u32(smem);
    int t = threadIdx.x;
    int lane = t & 31, wid = t >> 5;
    int m0 = blockIdx.y * 128, n0 = blockIdx.x * 128;
    int warp_m = (wid & 1) * 64;
    int warp_n = (wid >> 1) * 32;

    int cr0 = t >> 2,         cc0 = t & 3;
    int cr1 = (t + 256) >> 2, cc1 = (t + 256) & 3;

    const __nv_bfloat16* gsrc[4] = {Ah, Al, Bh, Bl};
    int grow0[4] = {m0, m0, n0, n0};

    float acc[4][4][4];
#pragma unroll
    for (int i = 0; i < 4; i++)
#pragma unroll
        for (int j = 0; j < 4; j++)
#pragma unroll
            for (int r = 0; r < 4; r++) acc[i][j][r] = 0.f;

#pragma unroll
    for (int tl = 0; tl < 4; tl++) {
        uint32_t tb = sb + tl * TILE_B;
        CP_ASYNC16(tb + cr0 * ROWB + cc0 * 16, gsrc[tl] + (size_t)(grow0[tl] + cr0) * DM + cc0 * 8);
        CP_ASYNC16(tb + cr1 * ROWB + cc1 * 16, gsrc[tl] + (size_t)(grow0[tl] + cr1) * DM + cc1 * 8);
    }
    CP_COMMIT();

    int arow = lane & 15;
    int akb  = (lane >> 4) * 16;
    int brow = (lane & 7) + ((lane >> 4) << 3);
    int bkb  = ((lane >> 3) & 1) * 16;

    for (int ch = 0; ch < NCHV; ch++) {
        int buf = ch & 1;
        uint32_t bufb = sb + buf * BUF_B;

        if (ch + 1 < NCHV) {
            uint32_t nb = sb + ((ch + 1) & 1) * BUF_B;
            int koff = (ch + 1) * KCHUNK;
#pragma unroll
            for (int tl = 0; tl < 4; tl++) {
                uint32_t tb = nb + tl * TILE_B;
                CP_ASYNC16(tb + cr0 * ROWB + cc0 * 16, gsrc[tl] + (size_t)(grow0[tl] + cr0) * DM + koff + cc0 * 8);
                CP_ASYNC16(tb + cr1 * ROWB + cc1 * 16, gsrc[tl] + (size_t)(grow0[tl] + cr1) * DM + koff + cc1 * 8);
            }
            CP_COMMIT();
            CP_WAIT1();
        } else {
            CP_WAIT0();
        }
        __syncthreads();

        uint32_t sAh = bufb + 0 * TILE_B;
        uint32_t sAl = bufb + 1 * TILE_B;
        uint32_t sBh = bufb + 2 * TILE_B;
        uint32_t sBl = bufb + 3 * TILE_B;

#pragma unroll
        for (int ks = 0; ks < 2; ks++) {
            int kb = ks * 32;
            uint32_t ah[4][4], al[4][4];
#pragma unroll
            for (int mt = 0; mt < 4; mt++) {
                uint32_t off = (uint32_t)((warp_m + mt * 16 + arow) * ROWB + kb + akb);
                LDMATRIX_X4(ah[mt][0], ah[mt][1], ah[mt][2], ah[mt][3], sAh + off);
                LDMATRIX_X4(al[mt][0], al[mt][1], al[mt][2], al[mt][3], sAl + off);
            }
#pragma unroll
            for (int np = 0; np < 2; np++) {
                uint32_t boff = (uint32_t)((warp_n + np * 16 + brow) * ROWB + kb + bkb);
                uint32_t bh[4], bl[4];
                LDMATRIX_X4(bh[0], bh[1], bh[2], bh[3], sBh + boff);
                LDMATRIX_X4(bl[0], bl[1], bl[2], bl[3], sBl + boff);
#pragma unroll
                for (int half = 0; half < 2; half++) {
                    int nt = np * 2 + half;
                    uint32_t bh0 = bh[half*2], bh1 = bh[half*2+1];
                    uint32_t bl0 = bl[half*2], bl1 = bl[half*2+1];
#pragma unroll
                    for (int mt = 0; mt < 4; mt++) {
                        float* d = acc[mt][nt];
                        MMA_BF16(d[0],d[1],d[2],d[3],
                                 ah[mt][0],ah[mt][1],ah[mt][2],ah[mt][3], bh0,bh1);
                        MMA_BF16(d[0],d[1],d[2],d[3],
                                 ah[mt][0],ah[mt][1],ah[mt][2],ah[mt][3], bl0,bl1);
                        MMA_BF16(d[0],d[1],d[2],d[3],
                                 al[mt][0],al[mt][1],al[mt][2],al[mt][3], bh0,bh1);
                    }
                }
            }
        }
        __syncthreads();
    }

    int g  = lane >> 2;
    int tg = lane & 3;
#pragma unroll
    for (int mt = 0; mt < 4; mt++) {
#pragma unroll
        for (int nt = 0; nt < 4; nt++) {
            int row = m0 + warp_m + mt * 16 + g;
            int col = n0 + warp_n + nt * 8 + tg * 2;
            float c0 = acc[mt][nt][0] * scale, c1 = acc[mt][nt][1] * scale;
            float c2 = acc[mt][nt][2] * scale, c3 = acc[mt][nt][3] * scale;
            if (!bf16out) {
                *(float2*)&C[(size_t)row * DM + col]       = make_float2(c0, c1);
                *(float2*)&C[(size_t)(row + 8) * DM + col] = make_float2(c2, c3);
            } else {
                uint32_t h0, l0, h1, l1;
                split2(c0, c1, h0, l0);
                split2(c2, c3, h1, l1);
                *(uint32_t*)&Ch[(size_t)row * DM + col]       = h0;
                *(uint32_t*)&Cl[(size_t)row * DM + col]       = l0;
                *(uint32_t*)&Ch[(size_t)(row + 8) * DM + col] = h1;
                *(uint32_t*)&Cl[(size_t)(row + 8) * DM + col] = l1;
            }
        }
    }
}

// ---------------- kernel 3: mma.sync flash attention, two-pass ----------------
// grid (SEQ/128, NH, BATCH), 256 threads (8 warps x 16 q-rows).
// Pass 1: scores (Q,K hi/lo split) + exp rowsums.
// Pass 2: scores again, write NORMALIZED attn fp32, PV (P,V hi/lo split),
//         write ctx directly as bf16 hi/lo.
#define AROWB 144
#define AMAT  (64 * AROWB)       // 9216
#define ABUF  (4 * AMAT)         // 36864 (Kh,Kl,Vth,Vtl)
#define ATTN_SMEM (2 * ABUF)     // 73728

__global__ void __launch_bounds__(256) attn_mma(
    const __nv_bfloat16* __restrict__ qh, const __nv_bfloat16* __restrict__ ql,
    const __nv_bfloat16* __restrict__ kh, const __nv_bfloat16* __restrict__ kl,
    const __nv_bfloat16* __restrict__ vth, const __nv_bfloat16* __restrict__ vtl,
    float* __restrict__ attn_out,
    __nv_bfloat16* __restrict__ cth, __nv_bfloat16* __restrict__ ctl)
{
    extern __shared__ char smem[];
    uint32_t sb = smem_u32(smem);
    int t = threadIdx.x, lane = t & 31, wid = t >> 5;
    int q0 = blockIdx.x * 128;
    int h  = blockIdx.y, b = blockIdx.z;
    int g  = lane >> 2, tg = lane & 3;

    size_t qoff = ((size_t)b * SEQ + q0) * DM + h * DKH;
    size_t koff = ((size_t)b * SEQ) * DM + h * DKH;
    size_t voff = ((size_t)(b * NH + h)) * DKH * SEQ;

    // ---- stage Q (128 rows x 64 bf16, hi+lo), ldmatrix into registers ----
#pragma unroll
    for (int i = 0; i < 4; i++) {
        int id = t + i * 256;            // 0..1023
        int r = id >> 3, c = id & 7;
        size_t gq = qoff + (size_t)r * DM + c * 8;
        CP_ASYNC16(sb + r * AROWB + c * 16,         qh + gq);
        CP_ASYNC16(sb + 18432 + r * AROWB + c * 16, ql + gq);
    }
    CP_COMMIT(); CP_WAIT0();
    __syncthreads();

    uint32_t aqh[4][4], aql[4][4];
    {
        int arow = lane & 15, akb = (lane >> 4) * 16;
        uint32_t qs = sb + (wid * 16 + arow) * AROWB + akb;
#pragma unroll
        for (int ks = 0; ks < 4; ks++) {
            LDMATRIX_X4(aqh[ks][0], aqh[ks][1], aqh[ks][2], aqh[ks][3], qs + ks * 32);
            LDMATRIX_X4(aql[ks][0], aql[ks][1], aql[ks][2], aql[ks][3], qs + 18432 + ks * 32);
        }
    }
    __syncthreads();

    int brow = (lane & 7) + ((lane >> 4) << 3);
    int bkb  = ((lane >> 3) & 1) * 16;

    auto load_k = [&](int kt, int buf) {
        uint32_t bb = sb + buf * ABUF;
#pragma unroll
        for (int i = 0; i < 2; i++) {
            int id = t + i * 256;
            int r = id >> 3, c = id & 7;
            size_t gk = koff + (size_t)(kt * 64 + r) * DM + c * 8;
            CP_ASYNC16(bb + r * AROWB + c * 16,        kh + gk);
            CP_ASYNC16(bb + AMAT + r * AROWB + c * 16, kl + gk);
        }
    };
    auto load_v = [&](int kt, int buf) {
        uint32_t bb = sb + buf * ABUF + 2 * AMAT;
#pragma unroll
        for (int i = 0; i < 2; i++) {
            int id = t + i * 256;
            int r = id >> 3, c = id & 7;
            size_t gv = voff + (size_t)r * SEQ + kt * 64 + c * 8;
            CP_ASYNC16(bb + r * AROWB + c * 16,        vth + gv);
            CP_ASYNC16(bb + AMAT + r * AROWB + c * 16, vtl + gv);
        }
    };

    // ================= pass 1: rowsums =================
    float l0 = 0.f, l1 = 0.f;
    load_k(0, 0); CP_COMMIT();
    for (int kt = 0; kt < SEQ / 64; kt++) {
        int buf = kt & 1;
        if (kt + 1 < SEQ / 64) { load_k(kt + 1, buf ^ 1); CP_COMMIT(); CP_WAIT1(); }
        else CP_WAIT0();
        __syncthreads();
        uint32_t sKh = sb + buf * ABUF, sKl = sKh + AMAT;
#pragma unroll
        for (int np = 0; np < 4; np++) {
            float s_acc[2][4] = {{0.f,0.f,0.f,0.f},{0.f,0.f,0.f,0.f}};
#pragma unroll
            for (int ks = 0; ks < 4; ks++) {
                uint32_t off = (uint32_t)((np * 16 + brow) * AROWB + ks * 32 + bkb);
                uint32_t bh[4], bl[4];
                LDMATRIX_X4(bh[0], bh[1], bh[2], bh[3], sKh + off);
                LDMATRIX_X4(bl[0], bl[1], bl[2], bl[3], sKl + off);
#pragma unroll
                for (int hf = 0; hf < 2; hf++) {
                    float* d = s_acc[hf];
                    MMA_BF16(d[0],d[1],d[2],d[3], aqh[ks][0],aqh[ks][1],aqh[ks][2],aqh[ks][3], bh[hf*2],bh[hf*2+1]);
                    MMA_BF16(d[0],d[1],d[2],d[3], aqh[ks][0],aqh[ks][1],aqh[ks][2],aqh[ks][3], bl[hf*2],bl[hf*2+1]);
                    MMA_BF16(d[0],d[1],d[2],d[3], aql[ks][0],aql[ks][1],aql[ks][2],aql[ks][3], bh[hf*2],bh[hf*2+1]);
                }
            }
#pragma unroll
            for (int hf = 0; hf < 2; hf++) {
                l0 += __expf(s_acc[hf][0]) + __expf(s_acc[hf][1]);
                l1 += __expf(s_acc[hf][2]) + __expf(s_acc[hf][3]);
            }
        }
        __syncthreads();
    }
    l0 += __shfl_xor_sync(0xffffffffu, l0, 1);
    l0 += __shfl_xor_sync(0xffffffffu, l0, 2);
    l1 += __shfl_xor_sync(0xffffffffu, l1, 1);
    l1 += __shfl_xor_sync(0xffffffffu, l1, 2);
    float inv0 = 1.f / l0, inv1 = 1.f / l1;

    // ================= pass 2: attn + PV =================
    float o_acc[8][4];
#pragma unroll
    for (int nt = 0; nt < 8; nt++)
#pragma unroll
        for (int r = 0; r < 4; r++) o_acc[nt][r] = 0.f;

    size_t abase = (((size_t)(b * NH + h)) * SEQ + q0 + wid * 16) * SEQ;

    load_k(0, 0); load_v(0, 0); CP_COMMIT();
    for (int kt = 0; kt < SEQ / 64; kt++) {
        int buf = kt & 1;
        if (kt + 1 < SEQ / 64) { load_k(kt + 1, buf ^ 1); load_v(kt + 1, buf ^ 1); CP_COMMIT(); CP_WAIT1(); }
        else CP_WAIT0();
        __syncthreads();
        uint32_t sKh = sb + buf * ABUF, sKl = sKh + AMAT;
        uint32_t sVh = sb + buf * ABUF + 2 * AMAT, sVl = sVh + AMAT;

        uint32_t ph[4][4], pl[4][4];
#pragma unroll
        for (int np = 0; np < 4; np++) {
            float s_acc[2][4] = {{0.f,0.f,0.f,0.f},{0.f,0.f,0.f,0.f}};
#pragma unroll
            for (int ks = 0; ks < 4; ks++) {
                uint32_t off = (uint32_t)((np * 16 + brow) * AROWB + ks * 32 + bkb);
                uint32_t bh[4], bl[4];
                LDMATRIX_X4(bh[0], bh[1], bh[2], bh[3], sKh + off);
                LDMATRIX_X4(bl[0], bl[1], bl[2], bl[3], sKl + off);
#pragma unroll
                for (int hf = 0; hf < 2; hf++) {
                    float* d = s_acc[hf];
                    MMA_BF16(d[0],d[1],d[2],d[3], aqh[ks][0],aqh[ks][1],aqh[ks][2],aqh[ks][3], bh[hf*2],bh[hf*2+1]);
                    MMA_BF16(d[0],d[1],d[2],d[3], aqh[ks][0],aqh[ks][1],aqh[ks][2],aqh[ks][3], bl[hf*2],bl[hf*2+1]);
                    MMA_BF16(d[0],d[1],d[2],d[3], aql[ks][0],aql[ks][1],aql[ks][2],aql[ks][3], bh[hf*2],bh[hf*2+1]);
                }
            }
#pragma unroll
            for (int hf = 0; hf < 2; hf++) {
                float p0 = __expf(s_acc[hf][0]) * inv0;
                float p1 = __expf(s_acc[hf][1]) * inv0;
                float p2 = __expf(s_acc[hf][2]) * inv1;
                float p3 = __expf(s_acc[hf][3]) * inv1;
                int col = kt * 64 + (np * 2 + hf) * 8 + tg * 2;
                *(float2*)&attn_out[abase + (size_t)g * SEQ + col]       = make_float2(p0, p1);
                *(float2*)&attn_out[abase + (size_t)(g + 8) * SEQ + col] = make_float2(p2, p3);
                split2(p0, p1, ph[np][hf * 2 + 0], pl[np][hf * 2 + 0]);
                split2(p2, p3, ph[np][hf * 2 + 1], pl[np][hf * 2 + 1]);
            }
        }

        // PV: A = P fragments (k = keys, 4 ksteps), B = Vt [d][key]
#pragma unroll
        for (int np = 0; np < 4; np++)
#pragma unroll
            for (int ks = 0; ks < 4; ks++) {
                uint32_t off = (uint32_t)((np * 16 + brow) * AROWB + ks * 32 + bkb);
                uint32_t bh[4], bl[4];
                LDMATRIX_X4(bh[0], bh[1], bh[2], bh[3], sVh + off);
                LDMATRIX_X4(bl[0], bl[1], bl[2], bl[3], sVl + off);
#pragma unroll
                for (int hf = 0; hf < 2; hf++) {
                    float* d = o_acc[np * 2 + hf];
                    MMA_BF16(d[0],d[1],d[2],d[3], ph[ks][0],ph[ks][1],ph[ks][2],ph[ks][3], bh[hf*2],bh[hf*2+1]);
                    MMA_BF16(d[0],d[1],d[2],d[3], ph[ks][0],ph[ks][1],ph[ks][2],ph[ks][3], bl[hf*2],bl[hf*2+1]);
                    MMA_BF16(d[0],d[1],d[2],d[3], pl[ks][0],pl[ks][1],pl[ks][2],pl[ks][3], bh[hf*2],bh[hf*2+1]);
                }
            }
        __syncthreads();
    }

    // write ctx as bf16 hi/lo
    size_t cbase = ((size_t)b * SEQ + q0 + wid * 16) * DM + h * DKH;
#pragma unroll
    for (int nt = 0; nt < 8; nt++) {
        int col = nt * 8 + tg * 2;
        uint32_t h0, l0w, h1, l1w;
        split2(o_acc[nt][0], o_acc[nt][1], h0, l0w);
        split2(o_acc[nt][2], o_acc[nt][3], h1, l1w);
        *(uint32_t*)&cth[cbase + (size_t)g * DM + col]       = h0;
        *(uint32_t*)&ctl[cbase + (size_t)g * DM + col]       = l0w;
        *(uint32_t*)&cth[cbase + (size_t)(g + 8) * DM + col] = h1;
        *(uint32_t*)&ctl[cbase + (size_t)(g + 8) * DM + col] = l1w;
    }
}

// ---------------- kernel 4: residual + LayerNorm ----------------
__global__ __launch_bounds__(256) void ln_kernel(const float* __restrict__ proj,
                                                 const float* __restrict__ resid,
                                                 const float* __restrict__ gamma,
                                                 const float* __restrict__ beta,
                                                 float* __restrict__ y)
{
    __shared__ float sred[16];
    int row = blockIdx.x;
    int t   = threadIdx.x;
    size_t base = (size_t)row * DM + t * 4;
    float4 pv = *(const float4*)&proj[base];
    float4 rv = *(const float4*)&resid[base];
    float4 vv = make_float4(pv.x+rv.x, pv.y+rv.y, pv.z+rv.z, pv.w+rv.w);
    float s  = vv.x + vv.y + vv.z + vv.w;
    float s2 = vv.x*vv.x + vv.y*vv.y + vv.z*vv.z + vv.w*vv.w;
#pragma unroll
    for (int off = 16; off; off >>= 1) {
        s  += __shfl_xor_sync(0xffffffffu, s,  off);
        s2 += __shfl_xor_sync(0xffffffffu, s2, off);
    }
    int warp = t >> 5, lane = t & 31;
    if (lane == 0) { sred[warp] = s; sred[8 + warp] = s2; }
    __syncthreads();
    if (t == 0) {
        float ts = 0.f, t2 = 0.f;
#pragma unroll
        for (int w = 0; w < 8; w++) { ts += sred[w]; t2 += sred[8 + w]; }
        float mean = ts * (1.0f / DM);
        float var  = t2 * (1.0f / DM) - mean * mean;
        sred[0] = mean;
        sred[1] = rsqrtf(var + 1e-6f);
    }
    __syncthreads();
    float mean = sred[0], rstd = sred[1];
    float4 g4 = *(const float4*)&gamma[t*4];
    float4 b4 = *(const float4*)&beta[t*4];
    float4 o;
    o.x = (vv.x - mean) * rstd * g4.x + b4.x;
    o.y = (vv.y - mean) * rstd * g4.y + b4.y;
    o.z = (vv.z - mean) * rstd * g4.z + b4.z;
    o.w = (vv.w - mean) * rstd * g4.w + b4.w;
    *(float4*)&y[base] = o;
}

// ---------------- launch ----------------
extern "C" void kernel_launch(void* const* d_in, const int* in_sizes, int n_in,
                              void* d_out, int out_size)
{
    const float* x     = (const float*)d_in[0];
    const float* Wq    = (const float*)d_in[1];
    const float* Wk    = (const float*)d_in[2];
    const float* Wv    = (const float*)d_in[3];
    const float* Wo    = (const float*)d_in[4];
    const float* gamma = (const float*)d_in[5];
    const float* beta  = (const float*)d_in[6];

    float* out      = (float*)d_out;
    float* y_out    = out;
    float* attn_out = out + (size_t)BATCH * SEQ * DM;

    float *xpe, *vb, *proj;
    cudaGetSymbolAddress((void**)&xpe,  g_xpe);
    cudaGetSymbolAddress((void**)&vb,   g_v);
    cudaGetSymbolAddress((void**)&proj, g_proj);

    __nv_bfloat16 *xh, *xl, *qh, *ql, *kh, *kl, *vth, *vtl, *ch, *cl;
    __nv_bfloat16 *wqh, *wql, *wkh, *wkl, *wvh, *wvl, *woh, *wol;
    cudaGetSymbolAddress((void**)&xh,  g_xh);
    cudaGetSymbolAddress((void**)&xl,  g_xl);
    cudaGetSymbolAddress((void**)&qh,  g_qh);
    cudaGetSymbolAddress((void**)&ql,  g_ql);
    cudaGetSymbolAddress((void**)&kh,  g_kh);
    cudaGetSymbolAddress((void**)&kl,  g_kl);
    cudaGetSymbolAddress((void**)&vth, g_vth);
    cudaGetSymbolAddress((void**)&vtl, g_vtl);
    cudaGetSymbolAddress((void**)&ch,  g_ch);
    cudaGetSymbolAddress((void**)&cl,  g_cl);
    cudaGetSymbolAddress((void**)&wqh, g_wqh);
    cudaGetSymbolAddress((void**)&wql, g_wql);
    cudaGetSymbolAddress((void**)&wkh, g_wkh);
    cudaGetSymbolAddress((void**)&wkl, g_wkl);
    cudaGetSymbolAddress((void**)&wvh, g_wvh);
    cudaGetSymbolAddress((void**)&wvl, g_wvl);
    cudaGetSymbolAddress((void**)&woh, g_woh);
    cudaGetSymbolAddress((void**)&wol, g_wol);

    cudaFuncSetAttribute(gemm_mma, cudaFuncAttributeMaxDynamicSharedMemorySize, GEMM_SMEM);
    cudaFuncSetAttribute(attn_mma, cudaFuncAttributeMaxDynamicSharedMemorySize, ATTN_SMEM);

    const int M = BATCH * SEQ;       // 4096
    const int NW4 = DM * DM / 4;
    dim3 ggrid(DM / 128, M / 128);

    pe_split<<<M, 256>>>(x, xpe, xh, xl);
    split_kernel<<<NW4 / 256, 256>>>(Wq, wqh, wql, NW4);
    split_kernel<<<NW4 / 256, 256>>>(Wk, wkh, wkl, NW4);
    split_kernel<<<NW4 / 256, 256>>>(Wv, wvh, wvl, NW4);
    split_kernel<<<NW4 / 256, 256>>>(Wo, woh, wol, NW4);

    gemm_mma<<<ggrid, 256, GEMM_SMEM>>>(xh, xl, wqh, wql, nullptr, qh, ql, 0.125f, 1);
    gemm_mma<<<ggrid, 256, GEMM_SMEM>>>(xh, xl, wkh, wkl, nullptr, kh, kl, 1.0f, 1);
    gemm_mma<<<ggrid, 256, GEMM_SMEM>>>(xh, xl, wvh, wvl, vb, nullptr, nullptr, 1.0f, 0);

    vtrans_kernel<<<dim3(SEQ / 64, DM / 32, BATCH), 256>>>(vb, vth, vtl);

    attn_mma<<<dim3(SEQ / 128, NH, BATCH), 256, ATTN_SMEM>>>(
        qh, ql, kh, kl, vth, vtl, attn_out, ch, cl);

    gemm_mma<<<ggrid, 256, GEMM_SMEM>>>(ch, cl, woh, wol, proj, nullptr, nullptr, 1.0f, 0);
    ln_kernel<<<M, 256>>>(proj, xpe, gamma, beta, y_out);
}

// round 6
// speedup vs baseline: 3.4213x; 1.2755x over previous
#include <cuda_runtime.h>
#include <cuda_fp16.h>
#include <math.h>
#include <stdint.h>

#define BATCH 4
#define SEQ   1024
#define DM    1024
#define NH    16
#define DKH   64

// ---------------- scratch (device globals: allocation-free) ----------------
__device__ float g_xpe [BATCH*SEQ*DM];
__device__ float g_proj[BATCH*SEQ*DM];

__device__ __half g_xh[BATCH*SEQ*DM], g_xl[BATCH*SEQ*DM];
__device__ __half g_qh[BATCH*SEQ*DM], g_ql[BATCH*SEQ*DM];
__device__ __half g_kh[BATCH*SEQ*DM];
__device__ __half g_vth[BATCH*SEQ*DM];
__device__ __half g_ch[BATCH*SEQ*DM], g_cl[BATCH*SEQ*DM];
__device__ __half g_wq[DM*DM], g_wk[DM*DM], g_wv[DM*DM], g_wo[DM*DM];

// ---------------- PTX helpers (plain sm_103-safe) ----------------
__device__ __forceinline__ uint32_t smem_u32(const void* p) {
    uint32_t a;
    asm("{ .reg .u64 t; cvta.to.shared.u64 t, %1; cvt.u32.u64 %0, t; }" : "=r"(a) : "l"(p));
    return a;
}

#define LDMATRIX_X4(r0,r1,r2,r3,addr) \
    asm volatile("ldmatrix.sync.aligned.m8n8.x4.shared.b16 {%0,%1,%2,%3}, [%4];" \
                 : "=r"(r0),"=r"(r1),"=r"(r2),"=r"(r3) : "r"(addr))

#define MMA_F16(d0,d1,d2,d3,a0,a1,a2,a3,b0,b1) \
    asm volatile("mma.sync.aligned.m16n8k16.row.col.f32.f16.f16.f32 " \
                 "{%0,%1,%2,%3}, {%4,%5,%6,%7}, {%8,%9}, {%0,%1,%2,%3};" \
                 : "+f"(d0),"+f"(d1),"+f"(d2),"+f"(d3) \
                 : "r"(a0),"r"(a1),"r"(a2),"r"(a3),"r"(b0),"r"(b1))

#define CP_ASYNC16(smem, gptr) \
    asm volatile("cp.async.cg.shared.global [%0], [%1], 16;" :: "r"(smem), "l"(gptr))
#define CP_COMMIT() asm volatile("cp.async.commit_group;")
#define CP_WAIT1()  asm volatile("cp.async.wait_group 1;")
#define CP_WAIT0()  asm volatile("cp.async.wait_group 0;")

// fp32 pair -> fp16 hi/lo packed regs
__device__ __forceinline__ void split2h(float x, float y, uint32_t& hi, uint32_t& lo) {
    __half hx = __float2half(x), hy = __float2half(y);
    __half lx = __float2half(x - __half2float(hx));
    __half ly = __float2half(y - __half2float(hy));
    __half2 h2 = __halves2half2(hx, hy);
    __half2 l2 = __halves2half2(lx, ly);
    hi = *reinterpret_cast<uint32_t*>(&h2);
    lo = *reinterpret_cast<uint32_t*>(&l2);
}

// ---------------- kernel 1: x + PE -> xpe fp32 AND xh/xl fp16 ----------------
__global__ __launch_bounds__(256) void pe_split(const float* __restrict__ x,
                                                float* __restrict__ xpe,
                                                __half* __restrict__ xh,
                                                __half* __restrict__ xl)
{
    int row = blockIdx.x;
    int t   = threadIdx.x;
    int s   = row & (SEQ - 1);
    float pos = (float)s;
    const float C = 9.210340371976184f / 1024.0f;
    size_t base = (size_t)row * DM + t * 4;
    float4 xv = *(const float4*)&x[base];
    int d0 = t * 4;
    float div0 = expf(-C * (float)d0);
    float div1 = expf(-C * (float)(d0 + 2));
    float a0 = pos * div0, a1 = pos * div1;
    float4 o;
    o.x = xv.x + sinf(a0);
    o.y = xv.y + cosf(a0);
    o.z = xv.z + sinf(a1);
    o.w = xv.w + cosf(a1);
    *(float4*)&xpe[base] = o;
    uint32_t h01, l01, h23, l23;
    split2h(o.x, o.y, h01, l01);
    split2h(o.z, o.w, h23, l23);
    *(uint2*)&xh[base] = make_uint2(h01, h23);
    *(uint2*)&xl[base] = make_uint2(l01, l23);
}

// ---------------- kernel: fp32 -> fp16 (weights, hi only) ----------------
__global__ __launch_bounds__(256) void h_convert(const float* __restrict__ s,
                                                 __half* __restrict__ d, int n4)
{
    int i = blockIdx.x * 256 + threadIdx.x;
    if (i >= n4) return;
    float4 v = ((const float4*)s)[i];
    __half2 a = __floats2half2_rn(v.x, v.y);
    __half2 b = __floats2half2_rn(v.z, v.w);
    ((uint2*)d)[i] = make_uint2(*reinterpret_cast<uint32_t*>(&a),
                                *reinterpret_cast<uint32_t*>(&b));
}

// ---------------- kernel 2: fp16 2-term GEMM  C = scale * (A @ B^T) ----------------
// A = Ah + Al (fp16 hi/lo), B = Bh (fp16). 2 MMAs per k-step.
// CTA tile 128x128, K-chunk 64, double-buffered cp.async.
#define KCHUNK 64
#define NCHV   (DM / KCHUNK)              // 16
#define ROWB   144                        // 128B data + 16B pad
#define TILE_B (128 * ROWB)               // 18432
#define BUF_B  (3 * TILE_B)               // Ah, Al, Bh
#define GEMM_SMEM (2 * BUF_B)             // 110592

#define OUT_F32 0
#define OUT_H2  1
#define OUT_H1  2
#define OUT_VT  3

__global__ void __launch_bounds__(256, 2) gemm_h(const __half* __restrict__ Ah,
                                                 const __half* __restrict__ Al,
                                                 const __half* __restrict__ Bh,
                                                 float* __restrict__ Cf,
                                                 __half* __restrict__ Ch,
                                                 __half* __restrict__ Cl,
                                                 float scale, int mode)
{
    extern __shared__ char smem[];
    uint32_t sb = smem_u32(smem);
    int t = threadIdx.x;
    int lane = t & 31, wid = t >> 5;
    int m0 = blockIdx.y * 128, n0 = blockIdx.x * 128;
    int warp_m = (wid & 1) * 64;
    int warp_n = (wid >> 1) * 32;

    float acc[4][4][4];
#pragma unroll
    for (int i = 0; i < 4; i++)
#pragma unroll
        for (int j = 0; j < 4; j++)
#pragma unroll
            for (int r = 0; r < 4; r++) acc[i][j][r] = 0.f;

    auto stage = [&](uint32_t bufb, int koff) {
#pragma unroll
        for (int i = 0; i < 4; i++) {
            int id = t + i * 256;          // 0..1023
            int r = id >> 3, c = id & 7;   // row, 16B chunk
            uint32_t so = r * ROWB + c * 16;
            CP_ASYNC16(bufb + 0 * TILE_B + so, Ah + (size_t)(m0 + r) * DM + koff + c * 8);
            CP_ASYNC16(bufb + 1 * TILE_B + so, Al + (size_t)(m0 + r) * DM + koff + c * 8);
            CP_ASYNC16(bufb + 2 * TILE_B + so, Bh + (size_t)(n0 + r) * DM + koff + c * 8);
        }
    };

    stage(sb, 0);
    CP_COMMIT();

    int arow = lane & 15;
    int akb  = (lane >> 4) * 16;
    int brow = (lane & 7) + ((lane >> 4) << 3);
    int bkb  = ((lane >> 3) & 1) * 16;

    for (int ch = 0; ch < NCHV; ch++) {
        int buf = ch & 1;
        uint32_t bufb = sb + buf * BUF_B;

        if (ch + 1 < NCHV) {
            stage(sb + ((ch + 1) & 1) * BUF_B, (ch + 1) * KCHUNK);
            CP_COMMIT();
            CP_WAIT1();
        } else {
            CP_WAIT0();
        }
        __syncthreads();

        uint32_t sAh = bufb + 0 * TILE_B;
        uint32_t sAl = bufb + 1 * TILE_B;
        uint32_t sBh = bufb + 2 * TILE_B;

#pragma unroll
        for (int ks = 0; ks < 4; ks++) {
            int kb = ks * 32;
            uint32_t ah[4][4], al[4][4];
#pragma unroll
            for (int mt = 0; mt < 4; mt++) {
                uint32_t off = (uint32_t)((warp_m + mt * 16 + arow) * ROWB + kb + akb);
                LDMATRIX_X4(ah[mt][0], ah[mt][1], ah[mt][2], ah[mt][3], sAh + off);
                LDMATRIX_X4(al[mt][0], al[mt][1], al[mt][2], al[mt][3], sAl + off);
            }
#pragma unroll
            for (int np = 0; np < 2; np++) {
                uint32_t boff = (uint32_t)((warp_n + np * 16 + brow) * ROWB + kb + bkb);
                uint32_t bh[4];
                LDMATRIX_X4(bh[0], bh[1], bh[2], bh[3], sBh + boff);
#pragma unroll
                for (int hf = 0; hf < 2; hf++) {
                    int nt = np * 2 + hf;
                    uint32_t b0 = bh[hf*2], b1 = bh[hf*2+1];
#pragma unroll
                    for (int mt = 0; mt < 4; mt++) {
                        float* d = acc[mt][nt];
                        MMA_F16(d[0],d[1],d[2],d[3],
                                ah[mt][0],ah[mt][1],ah[mt][2],ah[mt][3], b0,b1);
                        MMA_F16(d[0],d[1],d[2],d[3],
                                al[mt][0],al[mt][1],al[mt][2],al[mt][3], b0,b1);
                    }
                }
            }
        }
        __syncthreads();
    }

    // ---- epilogue ----
    int g  = lane >> 2;
    int tg = lane & 3;
#pragma unroll
    for (int mt = 0; mt < 4; mt++) {
#pragma unroll
        for (int nt = 0; nt < 4; nt++) {
            int row = m0 + warp_m + mt * 16 + g;
            int col = n0 + warp_n + nt * 8 + tg * 2;
            float c0 = acc[mt][nt][0] * scale, c1 = acc[mt][nt][1] * scale;
            float c2 = acc[mt][nt][2] * scale, c3 = acc[mt][nt][3] * scale;
            if (mode == OUT_F32) {
                *(float2*)&Cf[(size_t)row * DM + col]       = make_float2(c0, c1);
                *(float2*)&Cf[(size_t)(row + 8) * DM + col] = make_float2(c2, c3);
            } else if (mode == OUT_H2) {
                uint32_t h0, l0, h1, l1;
                split2h(c0, c1, h0, l0);
                split2h(c2, c3, h1, l1);
                *(uint32_t*)&Ch[(size_t)row * DM + col]       = h0;
                *(uint32_t*)&Cl[(size_t)row * DM + col]       = l0;
                *(uint32_t*)&Ch[(size_t)(row + 8) * DM + col] = h1;
                *(uint32_t*)&Cl[(size_t)(row + 8) * DM + col] = l1;
            } else if (mode == OUT_H1) {
                __half2 a = __floats2half2_rn(c0, c1);
                __half2 b = __floats2half2_rn(c2, c3);
                *(uint32_t*)&Ch[(size_t)row * DM + col]       = *reinterpret_cast<uint32_t*>(&a);
                *(uint32_t*)&Ch[(size_t)(row + 8) * DM + col] = *reinterpret_cast<uint32_t*>(&b);
            } else { // OUT_VT: Vt[b,h,dh,s] = C[row=token][col=dmodel]
                int b_ = row >> 10, s_ = row & (SEQ - 1);
                int h_ = col >> 6,  dh = col & 63;
                size_t vbase = (((size_t)(b_ * NH + h_)) * DKH + dh) * SEQ + s_;
                Ch[vbase]           = __float2half(c0);
                Ch[vbase + SEQ]     = __float2half(c1);
                Ch[vbase + 8]       = __float2half(c2);
                Ch[vbase + SEQ + 8] = __float2half(c3);
            }
        }
    }
}

// ---------------- kernel 3: fp16 mma flash attention, two-pass ----------------
// grid (SEQ/128, NH, BATCH), 256 threads (8 warps x 16 q-rows).
// Scores: Q(hi/lo) x Kh = 2 MMAs. PV: P(hi/lo) x Vh = 2 MMAs.
#define AROWB 144
#define AMAT  (64 * AROWB)        // 9216 (64 rows x 64 fp16)
#define QMAT  (128 * AROWB)       // 18432
#define ABUF  (2 * AMAT)          // Kh + Vth per buffer
#define AKV   (sb + 2 * QMAT)     // K/V region after Q hi/lo staging
#define ATTN_SMEM (2 * QMAT + 2 * ABUF)   // 73728

__global__ void __launch_bounds__(256, 2) attn_mma(
    const __half* __restrict__ qh, const __half* __restrict__ ql,
    const __half* __restrict__ kh, const __half* __restrict__ vth,
    float* __restrict__ attn_out,
    __half* __restrict__ cth, __half* __restrict__ ctl)
{
    extern __shared__ char smem[];
    uint32_t sb = smem_u32(smem);
    int t = threadIdx.x, lane = t & 31, wid = t >> 5;
    int q0 = blockIdx.x * 128;
    int h  = blockIdx.y, b = blockIdx.z;
    int g  = lane >> 2, tg = lane & 3;

    size_t qoff = ((size_t)b * SEQ + q0) * DM + h * DKH;
    size_t koff = ((size_t)b * SEQ) * DM + h * DKH;
    size_t voff = ((size_t)(b * NH + h)) * DKH * SEQ;

    // ---- stage Q (128 x 64 fp16 hi + lo), then ldmatrix to registers ----
#pragma unroll
    for (int i = 0; i < 4; i++) {
        int id = t + i * 256;
        int r = id >> 3, c = id & 7;
        size_t gq = qoff + (size_t)r * DM + c * 8;
        uint32_t so = r * AROWB + c * 16;
        CP_ASYNC16(sb + so,        qh + gq);
        CP_ASYNC16(sb + QMAT + so, ql + gq);
    }
    CP_COMMIT(); CP_WAIT0();
    __syncthreads();

    uint32_t aqh[4][4], aql[4][4];
    {
        int arow = lane & 15, akb = (lane >> 4) * 16;
        uint32_t qs = sb + (wid * 16 + arow) * AROWB + akb;
#pragma unroll
        for (int ks = 0; ks < 4; ks++) {
            LDMATRIX_X4(aqh[ks][0], aqh[ks][1], aqh[ks][2], aqh[ks][3], qs + ks * 32);
            LDMATRIX_X4(aql[ks][0], aql[ks][1], aql[ks][2], aql[ks][3], qs + QMAT + ks * 32);
        }
    }
    __syncthreads();

    int brow = (lane & 7) + ((lane >> 4) << 3);
    int bkb  = ((lane >> 3) & 1) * 16;

    auto load_k = [&](int kt, int buf) {
        uint32_t bb = AKV + buf * ABUF;
#pragma unroll
        for (int i = 0; i < 2; i++) {
            int id = t + i * 256;
            int r = id >> 3, c = id & 7;
            CP_ASYNC16(bb + r * AROWB + c * 16,
                       kh + koff + (size_t)(kt * 64 + r) * DM + c * 8);
        }
    };
    auto load_v = [&](int kt, int buf) {
        uint32_t bb = AKV + buf * ABUF + AMAT;
#pragma unroll
        for (int i = 0; i < 2; i++) {
            int id = t + i * 256;
            int r = id >> 3, c = id & 7;
            CP_ASYNC16(bb + r * AROWB + c * 16,
                       vth + voff + (size_t)r * SEQ + kt * 64 + c * 8);
        }
    };

    // ================= pass 1: rowsums =================
    float l0 = 0.f, l1 = 0.f;
    load_k(0, 0); CP_COMMIT();
    for (int kt = 0; kt < SEQ / 64; kt++) {
        int buf = kt & 1;
        if (kt + 1 < SEQ / 64) { load_k(kt + 1, buf ^ 1); CP_COMMIT(); CP_WAIT1(); }
        else CP_WAIT0();
        __syncthreads();
        uint32_t sKh = AKV + buf * ABUF;
#pragma unroll
        for (int np = 0; np < 4; np++) {
            float s_acc[2][4] = {{0.f,0.f,0.f,0.f},{0.f,0.f,0.f,0.f}};
#pragma unroll
            for (int ks = 0; ks < 4; ks++) {
                uint32_t off = (uint32_t)((np * 16 + brow) * AROWB + ks * 32 + bkb);
                uint32_t bh[4];
                LDMATRIX_X4(bh[0], bh[1], bh[2], bh[3], sKh + off);
#pragma unroll
                for (int hf = 0; hf < 2; hf++) {
                    float* d = s_acc[hf];
                    MMA_F16(d[0],d[1],d[2],d[3], aqh[ks][0],aqh[ks][1],aqh[ks][2],aqh[ks][3], bh[hf*2],bh[hf*2+1]);
                    MMA_F16(d[0],d[1],d[2],d[3], aql[ks][0],aql[ks][1],aql[ks][2],aql[ks][3], bh[hf*2],bh[hf*2+1]);
                }
            }
#pragma unroll
            for (int hf = 0; hf < 2; hf++) {
                l0 += __expf(s_acc[hf][0]) + __expf(s_acc[hf][1]);
                l1 += __expf(s_acc[hf][2]) + __expf(s_acc[hf][3]);
            }
        }
        __syncthreads();
    }
    l0 += __shfl_xor_sync(0xffffffffu, l0, 1);
    l0 += __shfl_xor_sync(0xffffffffu, l0, 2);
    l1 += __shfl_xor_sync(0xffffffffu, l1, 1);
    l1 += __shfl_xor_sync(0xffffffffu, l1, 2);
    float inv0 = 1.f / l0, inv1 = 1.f / l1;

    // ================= pass 2: attn + PV =================
    float o_acc[8][4];
#pragma unroll
    for (int nt = 0; nt < 8; nt++)
#pragma unroll
        for (int r = 0; r < 4; r++) o_acc[nt][r] = 0.f;

    size_t abase = (((size_t)(b * NH + h)) * SEQ + q0 + wid * 16) * SEQ;

    load_k(0, 0); load_v(0, 0); CP_COMMIT();
    for (int kt = 0; kt < SEQ / 64; kt++) {
        int buf = kt & 1;
        if (kt + 1 < SEQ / 64) { load_k(kt + 1, buf ^ 1); load_v(kt + 1, buf ^ 1); CP_COMMIT(); CP_WAIT1(); }
        else CP_WAIT0();
        __syncthreads();
        uint32_t sKh = AKV + buf * ABUF;
        uint32_t sVh = sKh + AMAT;

        uint32_t ph[4][4], pl[4][4];
#pragma unroll
        for (int np = 0; np < 4; np++) {
            float s_acc[2][4] = {{0.f,0.f,0.f,0.f},{0.f,0.f,0.f,0.f}};
#pragma unroll
            for (int ks = 0; ks < 4; ks++) {
                uint32_t off = (uint32_t)((np * 16 + brow) * AROWB + ks * 32 + bkb);
                uint32_t bh[4];
                LDMATRIX_X4(bh[0], bh[1], bh[2], bh[3], sKh + off);
#pragma unroll
                for (int hf = 0; hf < 2; hf++) {
                    float* d = s_acc[hf];
                    MMA_F16(d[0],d[1],d[2],d[3], aqh[ks][0],aqh[ks][1],aqh[ks][2],aqh[ks][3], bh[hf*2],bh[hf*2+1]);
                    MMA_F16(d[0],d[1],d[2],d[3], aql[ks][0],aql[ks][1],aql[ks][2],aql[ks][3], bh[hf*2],bh[hf*2+1]);
                }
            }
#pragma unroll
            for (int hf = 0; hf < 2; hf++) {
                float p0 = __expf(s_acc[hf][0]) * inv0;
                float p1 = __expf(s_acc[hf][1]) * inv0;
                float p2 = __expf(s_acc[hf][2]) * inv1;
                float p3 = __expf(s_acc[hf][3]) * inv1;
                int col = kt * 64 + (np * 2 + hf) * 8 + tg * 2;
                *(float2*)&attn_out[abase + (size_t)g * SEQ + col]       = make_float2(p0, p1);
                *(float2*)&attn_out[abase + (size_t)(g + 8) * SEQ + col] = make_float2(p2, p3);
                split2h(p0, p1, ph[np][hf * 2 + 0], pl[np][hf * 2 + 0]);
                split2h(p2, p3, ph[np][hf * 2 + 1], pl[np][hf * 2 + 1]);
            }
        }

        // PV: A = P fragments (ks = key-steps), B = Vt [d][key]
#pragma unroll
        for (int np = 0; np < 4; np++)
#pragma unroll
            for (int ks = 0; ks < 4; ks++) {
                uint32_t off = (uint32_t)((np * 16 + brow) * AROWB + ks * 32 + bkb);
                uint32_t bh[4];
                LDMATRIX_X4(bh[0], bh[1], bh[2], bh[3], sVh + off);
#pragma unroll
                for (int hf = 0; hf < 2; hf++) {
                    float* d = o_acc[np * 2 + hf];
                    MMA_F16(d[0],d[1],d[2],d[3], ph[ks][0],ph[ks][1],ph[ks][2],ph[ks][3], bh[hf*2],bh[hf*2+1]);
                    MMA_F16(d[0],d[1],d[2],d[3], pl[ks][0],pl[ks][1],pl[ks][2],pl[ks][3], bh[hf*2],bh[hf*2+1]);
                }
            }
        __syncthreads();
    }

    // write ctx as fp16 hi/lo
    size_t cbase = ((size_t)b * SEQ + q0 + wid * 16) * DM + h * DKH;
#pragma unroll
    for (int nt = 0; nt < 8; nt++) {
        int col = nt * 8 + tg * 2;
        uint32_t h0, l0w, h1, l1w;
        split2h(o_acc[nt][0], o_acc[nt][1], h0, l0w);
        split2h(o_acc[nt][2], o_acc[nt][3], h1, l1w);
        *(uint32_t*)&cth[cbase + (size_t)g * DM + col]       = h0;
        *(uint32_t*)&ctl[cbase + (size_t)g * DM + col]       = l0w;
        *(uint32_t*)&cth[cbase + (size_t)(g + 8) * DM + col] = h1;
        *(uint32_t*)&ctl[cbase + (size_t)(g + 8) * DM + col] = l1w;
    }
}

// ---------------- kernel 4: residual + LayerNorm ----------------
__global__ __launch_bounds__(256) void ln_kernel(const float* __restrict__ proj,
                                                 const float* __restrict__ resid,
                                                 const float* __restrict__ gamma,
                                                 const float* __restrict__ beta,
                                                 float* __restrict__ y)
{
    __shared__ float sred[16];
    int row = blockIdx.x;
    int t   = threadIdx.x;
    size_t base = (size_t)row * DM + t * 4;
    float4 pv = *(const float4*)&proj[base];
    float4 rv = *(const float4*)&resid[base];
    float4 vv = make_float4(pv.x+rv.x, pv.y+rv.y, pv.z+rv.z, pv.w+rv.w);
    float s  = vv.x + vv.y + vv.z + vv.w;
    float s2 = vv.x*vv.x + vv.y*vv.y + vv.z*vv.z + vv.w*vv.w;
#pragma unroll
    for (int off = 16; off; off >>= 1) {
        s  += __shfl_xor_sync(0xffffffffu, s,  off);
        s2 += __shfl_xor_sync(0xffffffffu, s2, off);
    }
    int warp = t >> 5, lane = t & 31;
    if (lane == 0) { sred[warp] = s; sred[8 + warp] = s2; }
    __syncthreads();
    if (t == 0) {
        float ts = 0.f, t2 = 0.f;
#pragma unroll
        for (int w = 0; w < 8; w++) { ts += sred[w]; t2 += sred[8 + w]; }
        float mean = ts * (1.0f / DM);
        float var  = t2 * (1.0f / DM) - mean * mean;
        sred[0] = mean;
        sred[1] = rsqrtf(var + 1e-6f);
    }
    __syncthreads();
    float mean = sred[0], rstd = sred[1];
    float4 g4 = *(const float4*)&gamma[t*4];
    float4 b4 = *(const float4*)&beta[t*4];
    float4 o;
    o.x = (vv.x - mean) * rstd * g4.x + b4.x;
    o.y = (vv.y - mean) * rstd * g4.y + b4.y;
    o.z = (vv.z - mean) * rstd * g4.z + b4.z;
    o.w = (vv.w - mean) * rstd * g4.w + b4.w;
    *(float4*)&y[base] = o;
}

// ---------------- launch ----------------
extern "C" void kernel_launch(void* const* d_in, const int* in_sizes, int n_in,
                              void* d_out, int out_size)
{
    const float* x     = (const float*)d_in[0];
    const float* Wq    = (const float*)d_in[1];
    const float* Wk    = (const float*)d_in[2];
    const float* Wv    = (const float*)d_in[3];
    const float* Wo    = (const float*)d_in[4];
    const float* gamma = (const float*)d_in[5];
    const float* beta  = (const float*)d_in[6];

    float* out      = (float*)d_out;
    float* y_out    = out;
    float* attn_out = out + (size_t)BATCH * SEQ * DM;

    float *xpe, *proj;
    cudaGetSymbolAddress((void**)&xpe,  g_xpe);
    cudaGetSymbolAddress((void**)&proj, g_proj);

    __half *xh, *xl, *qh, *ql, *kh, *vth, *ch, *cl, *wq, *wk, *wv, *wo;
    cudaGetSymbolAddress((void**)&xh,  g_xh);
    cudaGetSymbolAddress((void**)&xl,  g_xl);
    cudaGetSymbolAddress((void**)&qh,  g_qh);
    cudaGetSymbolAddress((void**)&ql,  g_ql);
    cudaGetSymbolAddress((void**)&kh,  g_kh);
    cudaGetSymbolAddress((void**)&vth, g_vth);
    cudaGetSymbolAddress((void**)&ch,  g_ch);
    cudaGetSymbolAddress((void**)&cl,  g_cl);
    cudaGetSymbolAddress((void**)&wq,  g_wq);
    cudaGetSymbolAddress((void**)&wk,  g_wk);
    cudaGetSymbolAddress((void**)&wv,  g_wv);
    cudaGetSymbolAddress((void**)&wo,  g_wo);

    cudaFuncSetAttribute(gemm_h,   cudaFuncAttributeMaxDynamicSharedMemorySize, GEMM_SMEM);
    cudaFuncSetAttribute(attn_mma, cudaFuncAttributeMaxDynamicSharedMemorySize, ATTN_SMEM);

    const int M = BATCH * SEQ;       // 4096
    const int NW4 = DM * DM / 4;     // 262144
    dim3 ggrid(DM / 128, M / 128);   // (8, 32)

    pe_split<<<M, 256>>>(x, xpe, xh, xl);
    h_convert<<<NW4 / 256, 256>>>(Wq, wq, NW4);
    h_convert<<<NW4 / 256, 256>>>(Wk, wk, NW4);
    h_convert<<<NW4 / 256, 256>>>(Wv, wv, NW4);
    h_convert<<<NW4 / 256, 256>>>(Wo, wo, NW4);

    gemm_h<<<ggrid, 256, GEMM_SMEM>>>(xh, xl, wq, nullptr, qh, ql, 0.125f, OUT_H2);
    gemm_h<<<ggrid, 256, GEMM_SMEM>>>(xh, xl, wk, nullptr, kh, nullptr, 1.0f, OUT_H1);
    gemm_h<<<ggrid, 256, GEMM_SMEM>>>(xh, xl, wv, nullptr, vth, nullptr, 1.0f, OUT_VT);

    attn_mma<<<dim3(SEQ / 128, NH, BATCH), 256, ATTN_SMEM>>>(
        qh, ql, kh, vth, attn_out, ch, cl);

    gemm_h<<<ggrid, 256, GEMM_SMEM>>>(ch, cl, wo, proj, nullptr, nullptr, 1.0f, OUT_F32);
    ln_kernel<<<M, 256>>>(proj, xpe, gamma, beta, y_out);
}

// round 7
// speedup vs baseline: 5.8750x; 1.7172x over previous
#include <cuda_runtime.h>
#include <cuda_fp16.h>
#include <math.h>
#include <stdint.h>

#define BATCH 4
#define SEQ   1024
#define DM    1024
#define NH    16
#define DKH   64

// ---------------- scratch (device globals: allocation-free) ----------------
__device__ float g_xpe [BATCH*SEQ*DM];
__device__ float g_proj[BATCH*SEQ*DM];

__device__ __half g_xh[BATCH*SEQ*DM], g_xl[BATCH*SEQ*DM];
__device__ __half g_qh[BATCH*SEQ*DM];
__device__ __half g_kh[BATCH*SEQ*DM];
__device__ __half g_vth[BATCH*SEQ*DM];
__device__ __half g_ch[BATCH*SEQ*DM];
__device__ __half g_wq[DM*DM], g_wk[DM*DM], g_wv[DM*DM], g_wo[DM*DM];

// ---------------- PTX helpers (plain sm_103-safe) ----------------
__device__ __forceinline__ uint32_t smem_u32(const void* p) {
    uint32_t a;
    asm("{ .reg .u64 t; cvta.to.shared.u64 t, %1; cvt.u32.u64 %0, t; }" : "=r"(a) : "l"(p));
    return a;
}

#define LDMATRIX_X4(r0,r1,r2,r3,addr) \
    asm volatile("ldmatrix.sync.aligned.m8n8.x4.shared.b16 {%0,%1,%2,%3}, [%4];" \
                 : "=r"(r0),"=r"(r1),"=r"(r2),"=r"(r3) : "r"(addr))

#define MMA_F16(d0,d1,d2,d3,a0,a1,a2,a3,b0,b1) \
    asm volatile("mma.sync.aligned.m16n8k16.row.col.f32.f16.f16.f32 " \
                 "{%0,%1,%2,%3}, {%4,%5,%6,%7}, {%8,%9}, {%0,%1,%2,%3};" \
                 : "+f"(d0),"+f"(d1),"+f"(d2),"+f"(d3) \
                 : "r"(a0),"r"(a1),"r"(a2),"r"(a3),"r"(b0),"r"(b1))

#define CP_ASYNC16(smem, gptr) \
    asm volatile("cp.async.cg.shared.global [%0], [%1], 16;" :: "r"(smem), "l"(gptr))
#define CP_COMMIT() asm volatile("cp.async.commit_group;")
#define CP_WAIT1()  asm volatile("cp.async.wait_group 1;")
#define CP_WAIT0()  asm volatile("cp.async.wait_group 0;")

// fp32 pair -> fp16 hi/lo packed regs
__device__ __forceinline__ void split2h(float x, float y, uint32_t& hi, uint32_t& lo) {
    __half hx = __float2half(x), hy = __float2half(y);
    __half lx = __float2half(x - __half2float(hx));
    __half ly = __float2half(y - __half2float(hy));
    __half2 h2 = __halves2half2(hx, hy);
    __half2 l2 = __halves2half2(lx, ly);
    hi = *reinterpret_cast<uint32_t*>(&h2);
    lo = *reinterpret_cast<uint32_t*>(&l2);
}
__device__ __forceinline__ uint32_t pack2h(float x, float y) {
    __half2 h2 = __floats2half2_rn(x, y);
    return *reinterpret_cast<uint32_t*>(&h2);
}

// ---------------- kernel 1: x + PE -> xpe fp32 AND xh/xl fp16 ----------------
__global__ __launch_bounds__(256) void pe_split(const float* __restrict__ x,
                                                float* __restrict__ xpe,
                                                __half* __restrict__ xh,
                                                __half* __restrict__ xl)
{
    int row = blockIdx.x;
    int t   = threadIdx.x;
    int s   = row & (SEQ - 1);
    float pos = (float)s;
    const float C = 9.210340371976184f / 1024.0f;
    size_t base = (size_t)row * DM + t * 4;
    float4 xv = *(const float4*)&x[base];
    int d0 = t * 4;
    float div0 = expf(-C * (float)d0);
    float div1 = expf(-C * (float)(d0 + 2));
    float a0 = pos * div0, a1 = pos * div1;
    float4 o;
    o.x = xv.x + sinf(a0);
    o.y = xv.y + cosf(a0);
    o.z = xv.z + sinf(a1);
    o.w = xv.w + cosf(a1);
    *(float4*)&xpe[base] = o;
    uint32_t h01, l01, h23, l23;
    split2h(o.x, o.y, h01, l01);
    split2h(o.z, o.w, h23, l23);
    *(uint2*)&xh[base] = make_uint2(h01, h23);
    *(uint2*)&xl[base] = make_uint2(l01, l23);
}

// ---------------- kernel: 4 weight matrices fp32 -> fp16 in one launch ----------------
__global__ __launch_bounds__(256) void h_convert4(const float* __restrict__ s0,
                                                  const float* __restrict__ s1,
                                                  const float* __restrict__ s2,
                                                  const float* __restrict__ s3,
                                                  __half* __restrict__ d0,
                                                  __half* __restrict__ d1,
                                                  __half* __restrict__ d2,
                                                  __half* __restrict__ d3,
                                                  int n4)
{
    int i = blockIdx.x * 256 + threadIdx.x;
    if (i >= n4) return;
    const float* s; __half* d;
    switch (blockIdx.y) {
        case 0: s = s0; d = d0; break;
        case 1: s = s1; d = d1; break;
        case 2: s = s2; d = d2; break;
        default: s = s3; d = d3; break;
    }
    float4 v = ((const float4*)s)[i];
    ((uint2*)d)[i] = make_uint2(pack2h(v.x, v.y), pack2h(v.z, v.w));
}

// ---------------- kernel 2: fp16 GEMM  C = scale * (A @ B^T) ----------------
// NTERMS=2: A = Ah + Al (hi/lo). NTERMS=1: A = Ah only. B always hi-only.
#define KCHUNK 64
#define NCHV   (DM / KCHUNK)              // 16
#define ROWB   144                        // 128B data + 16B pad
#define TILE_B (128 * ROWB)               // 18432

#define OUT_F32 0
#define OUT_H1  1
#define OUT_VT  2

template<int NTERMS, int MODE>
__global__ void __launch_bounds__(256, 2) gemm_h(const __half* __restrict__ Ah,
                                                 const __half* __restrict__ Al,
                                                 const __half* __restrict__ Bh,
                                                 float* __restrict__ Cf,
                                                 __half* __restrict__ Ch,
                                                 float scale)
{
    constexpr int NTILES = NTERMS + 1;          // Ah[,Al],Bh
    constexpr int BUF_B  = NTILES * TILE_B;
    extern __shared__ char smem[];
    uint32_t sb = smem_u32(smem);
    int t = threadIdx.x;
    int lane = t & 31, wid = t >> 5;
    int m0 = blockIdx.y * 128, n0 = blockIdx.x * 128;
    int warp_m = (wid & 1) * 64;
    int warp_n = (wid >> 1) * 32;

    float acc[4][4][4];
#pragma unroll
    for (int i = 0; i < 4; i++)
#pragma unroll
        for (int j = 0; j < 4; j++)
#pragma unroll
            for (int r = 0; r < 4; r++) acc[i][j][r] = 0.f;

    auto stage = [&](uint32_t bufb, int koff) {
#pragma unroll
        for (int i = 0; i < 4; i++) {
            int id = t + i * 256;          // 0..1023
            int r = id >> 3, c = id & 7;   // row, 16B chunk
            uint32_t so = r * ROWB + c * 16;
            CP_ASYNC16(bufb + so, Ah + (size_t)(m0 + r) * DM + koff + c * 8);
            if (NTERMS == 2)
                CP_ASYNC16(bufb + TILE_B + so, Al + (size_t)(m0 + r) * DM + koff + c * 8);
            CP_ASYNC16(bufb + (NTILES - 1) * TILE_B + so, Bh + (size_t)(n0 + r) * DM + koff + c * 8);
        }
    };

    stage(sb, 0);
    CP_COMMIT();

    int arow = lane & 15;
    int akb  = (lane >> 4) * 16;
    int brow = (lane & 7) + ((lane >> 4) << 3);
    int bkb  = ((lane >> 3) & 1) * 16;

    for (int ch = 0; ch < NCHV; ch++) {
        int buf = ch & 1;
        uint32_t bufb = sb + buf * BUF_B;

        if (ch + 1 < NCHV) {
            stage(sb + ((ch + 1) & 1) * BUF_B, (ch + 1) * KCHUNK);
            CP_COMMIT();
            CP_WAIT1();
        } else {
            CP_WAIT0();
        }
        __syncthreads();

        uint32_t sAh = bufb;
        uint32_t sAl = bufb + TILE_B;
        uint32_t sBh = bufb + (NTILES - 1) * TILE_B;

#pragma unroll
        for (int ks = 0; ks < 4; ks++) {
            int kb = ks * 32;
            uint32_t ah[4][4], al[4][4];
#pragma unroll
            for (int mt = 0; mt < 4; mt++) {
                uint32_t off = (uint32_t)((warp_m + mt * 16 + arow) * ROWB + kb + akb);
                LDMATRIX_X4(ah[mt][0], ah[mt][1], ah[mt][2], ah[mt][3], sAh + off);
                if (NTERMS == 2)
                    LDMATRIX_X4(al[mt][0], al[mt][1], al[mt][2], al[mt][3], sAl + off);
            }
#pragma unroll
            for (int np = 0; np < 2; np++) {
                uint32_t boff = (uint32_t)((warp_n + np * 16 + brow) * ROWB + kb + bkb);
                uint32_t bh[4];
                LDMATRIX_X4(bh[0], bh[1], bh[2], bh[3], sBh + boff);
#pragma unroll
                for (int hf = 0; hf < 2; hf++) {
                    int nt = np * 2 + hf;
                    uint32_t b0 = bh[hf*2], b1 = bh[hf*2+1];
#pragma unroll
                    for (int mt = 0; mt < 4; mt++) {
                        float* d = acc[mt][nt];
                        MMA_F16(d[0],d[1],d[2],d[3],
                                ah[mt][0],ah[mt][1],ah[mt][2],ah[mt][3], b0,b1);
                        if (NTERMS == 2)
                            MMA_F16(d[0],d[1],d[2],d[3],
                                    al[mt][0],al[mt][1],al[mt][2],al[mt][3], b0,b1);
                    }
                }
            }
        }
        __syncthreads();
    }

    // ---- epilogue ----
    int g  = lane >> 2;
    int tg = lane & 3;
#pragma unroll
    for (int mt = 0; mt < 4; mt++) {
#pragma unroll
        for (int nt = 0; nt < 4; nt++) {
            int row = m0 + warp_m + mt * 16 + g;
            int col = n0 + warp_n + nt * 8 + tg * 2;
            float c0 = acc[mt][nt][0] * scale, c1 = acc[mt][nt][1] * scale;
            float c2 = acc[mt][nt][2] * scale, c3 = acc[mt][nt][3] * scale;
            if (MODE == OUT_F32) {
                *(float2*)&Cf[(size_t)row * DM + col]       = make_float2(c0, c1);
                *(float2*)&Cf[(size_t)(row + 8) * DM + col] = make_float2(c2, c3);
            } else if (MODE == OUT_H1) {
                *(uint32_t*)&Ch[(size_t)row * DM + col]       = pack2h(c0, c1);
                *(uint32_t*)&Ch[(size_t)(row + 8) * DM + col] = pack2h(c2, c3);
            } else { // OUT_VT: Vt[b,h,dh,s] = C[row=token][col=dmodel]
                int b_ = row >> 10, s_ = row & (SEQ - 1);
                int h_ = col >> 6,  dh = col & 63;
                size_t vbase = (((size_t)(b_ * NH + h_)) * DKH + dh) * SEQ + s_;
                Ch[vbase]           = __float2half(c0);
                Ch[vbase + SEQ]     = __float2half(c1);
                Ch[vbase + 8]       = __float2half(c2);
                Ch[vbase + SEQ + 8] = __float2half(c3);
            }
        }
    }
}

// ---------------- kernel 3: fp16 mma flash attention, two-pass, hi-only ----------------
// grid (SEQ/128, NH, BATCH), 256 threads (8 warps x 16 q-rows).
// Scores: Qh x Kh = 1 MMA/kstep. PV: Ph x Vh = 1 MMA/kstep.
#define AROWB 144
#define AMAT  (64 * AROWB)        // 9216 (64 rows x 64 fp16)
#define QMAT  (128 * AROWB)       // 18432
#define ABUF  (2 * AMAT)          // Kh + Vth per buffer
#define AKV   (sb + QMAT)         // K/V region after Q staging
#define ATTN_SMEM (QMAT + 2 * ABUF)   // 55296

__global__ void __launch_bounds__(256, 2) attn_mma(
    const __half* __restrict__ qh,
    const __half* __restrict__ kh, const __half* __restrict__ vth,
    float* __restrict__ attn_out,
    __half* __restrict__ cth)
{
    extern __shared__ char smem[];
    uint32_t sb = smem_u32(smem);
    int t = threadIdx.x, lane = t & 31, wid = t >> 5;
    int q0 = blockIdx.x * 128;
    int h  = blockIdx.y, b = blockIdx.z;
    int g  = lane >> 2, tg = lane & 3;

    size_t qoff = ((size_t)b * SEQ + q0) * DM + h * DKH;
    size_t koff = ((size_t)b * SEQ) * DM + h * DKH;
    size_t voff = ((size_t)(b * NH + h)) * DKH * SEQ;

    // ---- stage Q (128 x 64 fp16), then ldmatrix to registers ----
#pragma unroll
    for (int i = 0; i < 4; i++) {
        int id = t + i * 256;
        int r = id >> 3, c = id & 7;
        CP_ASYNC16(sb + r * AROWB + c * 16, qh + qoff + (size_t)r * DM + c * 8);
    }
    CP_COMMIT(); CP_WAIT0();
    __syncthreads();

    uint32_t aqh[4][4];
    {
        int arow = lane & 15, akb = (lane >> 4) * 16;
        uint32_t qs = sb + (wid * 16 + arow) * AROWB + akb;
#pragma unroll
        for (int ks = 0; ks < 4; ks++)
            LDMATRIX_X4(aqh[ks][0], aqh[ks][1], aqh[ks][2], aqh[ks][3], qs + ks * 32);
    }
    __syncthreads();

    int brow = (lane & 7) + ((lane >> 4) << 3);
    int bkb  = ((lane >> 3) & 1) * 16;

    auto load_k = [&](int kt, int buf) {
        uint32_t bb = AKV + buf * ABUF;
#pragma unroll
        for (int i = 0; i < 2; i++) {
            int id = t + i * 256;
            int r = id >> 3, c = id & 7;
            CP_ASYNC16(bb + r * AROWB + c * 16,
                       kh + koff + (size_t)(kt * 64 + r) * DM + c * 8);
        }
    };
    auto load_v = [&](int kt, int buf) {
        uint32_t bb = AKV + buf * ABUF + AMAT;
#pragma unroll
        for (int i = 0; i < 2; i++) {
            int id = t + i * 256;
            int r = id >> 3, c = id & 7;
            CP_ASYNC16(bb + r * AROWB + c * 16,
                       vth + voff + (size_t)r * SEQ + kt * 64 + c * 8);
        }
    };

    // ================= pass 1: rowsums =================
    float l0 = 0.f, l1 = 0.f;
    load_k(0, 0); CP_COMMIT();
    for (int kt = 0; kt < SEQ / 64; kt++) {
        int buf = kt & 1;
        if (kt + 1 < SEQ / 64) { load_k(kt + 1, buf ^ 1); CP_COMMIT(); CP_WAIT1(); }
        else CP_WAIT0();
        __syncthreads();
        uint32_t sKh = AKV + buf * ABUF;
#pragma unroll
        for (int np = 0; np < 4; np++) {
            float s_acc[2][4] = {{0.f,0.f,0.f,0.f},{0.f,0.f,0.f,0.f}};
#pragma unroll
            for (int ks = 0; ks < 4; ks++) {
                uint32_t off = (uint32_t)((np * 16 + brow) * AROWB + ks * 32 + bkb);
                uint32_t bh[4];
                LDMATRIX_X4(bh[0], bh[1], bh[2], bh[3], sKh + off);
#pragma unroll
                for (int hf = 0; hf < 2; hf++) {
                    float* d = s_acc[hf];
                    MMA_F16(d[0],d[1],d[2],d[3], aqh[ks][0],aqh[ks][1],aqh[ks][2],aqh[ks][3], bh[hf*2],bh[hf*2+1]);
                }
            }
#pragma unroll
            for (int hf = 0; hf < 2; hf++) {
                l0 += __expf(s_acc[hf][0]) + __expf(s_acc[hf][1]);
                l1 += __expf(s_acc[hf][2]) + __expf(s_acc[hf][3]);
            }
        }
        __syncthreads();
    }
    l0 += __shfl_xor_sync(0xffffffffu, l0, 1);
    l0 += __shfl_xor_sync(0xffffffffu, l0, 2);
    l1 += __shfl_xor_sync(0xffffffffu, l1, 1);
    l1 += __shfl_xor_sync(0xffffffffu, l1, 2);
    float inv0 = 1.f / l0, inv1 = 1.f / l1;

    // ================= pass 2: attn + PV =================
    float o_acc[8][4];
#pragma unroll
    for (int nt = 0; nt < 8; nt++)
#pragma unroll
        for (int r = 0; r < 4; r++) o_acc[nt][r] = 0.f;

    size_t abase = (((size_t)(b * NH + h)) * SEQ + q0 + wid * 16) * SEQ;

    load_k(0, 0); load_v(0, 0); CP_COMMIT();
    for (int kt = 0; kt < SEQ / 64; kt++) {
        int buf = kt & 1;
        if (kt + 1 < SEQ / 64) { load_k(kt + 1, buf ^ 1); load_v(kt + 1, buf ^ 1); CP_COMMIT(); CP_WAIT1(); }
        else CP_WAIT0();
        __syncthreads();
        uint32_t sKh = AKV + buf * ABUF;
        uint32_t sVh = sKh + AMAT;

        uint32_t ph[4][4];
#pragma unroll
        for (int np = 0; np < 4; np++) {
            float s_acc[2][4] = {{0.f,0.f,0.f,0.f},{0.f,0.f,0.f,0.f}};
#pragma unroll
            for (int ks = 0; ks < 4; ks++) {
                uint32_t off = (uint32_t)((np * 16 + brow) * AROWB + ks * 32 + bkb);
                uint32_t bh[4];
                LDMATRIX_X4(bh[0], bh[1], bh[2], bh[3], sKh + off);
#pragma unroll
                for (int hf = 0; hf < 2; hf++) {
                    float* d = s_acc[hf];
                    MMA_F16(d[0],d[1],d[2],d[3], aqh[ks][0],aqh[ks][1],aqh[ks][2],aqh[ks][3], bh[hf*2],bh[hf*2+1]);
                }
            }
#pragma unroll
            for (int hf = 0; hf < 2; hf++) {
                float p0 = __expf(s_acc[hf][0]) * inv0;
                float p1 = __expf(s_acc[hf][1]) * inv0;
                float p2 = __expf(s_acc[hf][2]) * inv1;
                float p3 = __expf(s_acc[hf][3]) * inv1;
                int col = kt * 64 + (np * 2 + hf) * 8 + tg * 2;
                *(float2*)&attn_out[abase + (size_t)g * SEQ + col]       = make_float2(p0, p1);
                *(float2*)&attn_out[abase + (size_t)(g + 8) * SEQ + col] = make_float2(p2, p3);
                ph[np][hf * 2 + 0] = pack2h(p0, p1);
                ph[np][hf * 2 + 1] = pack2h(p2, p3);
            }
        }

        // PV: A = P fragments (ks = key-steps), B = Vt [d][key]
#pragma unroll
        for (int np = 0; np < 4; np++)
#pragma unroll
            for (int ks = 0; ks < 4; ks++) {
                uint32_t off = (uint32_t)((np * 16 + brow) * AROWB + ks * 32 + bkb);
                uint32_t bh[4];
                LDMATRIX_X4(bh[0], bh[1], bh[2], bh[3], sVh + off);
#pragma unroll
                for (int hf = 0; hf < 2; hf++) {
                    float* d = o_acc[np * 2 + hf];
                    MMA_F16(d[0],d[1],d[2],d[3], ph[ks][0],ph[ks][1],ph[ks][2],ph[ks][3], bh[hf*2],bh[hf*2+1]);
                }
            }
        __syncthreads();
    }

    // write ctx as fp16 (hi only)
    size_t cbase = ((size_t)b * SEQ + q0 + wid * 16) * DM + h * DKH;
#pragma unroll
    for (int nt = 0; nt < 8; nt++) {
        int col = nt * 8 + tg * 2;
        *(uint32_t*)&cth[cbase + (size_t)g * DM + col]       = pack2h(o_acc[nt][0], o_acc[nt][1]);
        *(uint32_t*)&cth[cbase + (size_t)(g + 8) * DM + col] = pack2h(o_acc[nt][2], o_acc[nt][3]);
    }
}

// ---------------- kernel 4: residual + LayerNorm ----------------
__global__ __launch_bounds__(256) void ln_kernel(const float* __restrict__ proj,
                                                 const float* __restrict__ resid,
                                                 const float* __restrict__ gamma,
                                                 const float* __restrict__ beta,
                                                 float* __restrict__ y)
{
    __shared__ float sred[16];
    int row = blockIdx.x;
    int t   = threadIdx.x;
    size_t base = (size_t)row * DM + t * 4;
    float4 pv = *(const float4*)&proj[base];
    float4 rv = *(const float4*)&resid[base];
    float4 vv = make_float4(pv.x+rv.x, pv.y+rv.y, pv.z+rv.z, pv.w+rv.w);
    float s  = vv.x + vv.y + vv.z + vv.w;
    float s2 = vv.x*vv.x + vv.y*vv.y + vv.z*vv.z + vv.w*vv.w;
#pragma unroll
    for (int off = 16; off; off >>= 1) {
        s  += __shfl_xor_sync(0xffffffffu, s,  off);
        s2 += __shfl_xor_sync(0xffffffffu, s2, off);
    }
    int warp = t >> 5, lane = t & 31;
    if (lane == 0) { sred[warp] = s; sred[8 + warp] = s2; }
    __syncthreads();
    if (t == 0) {
        float ts = 0.f, t2 = 0.f;
#pragma unroll
        for (int w = 0; w < 8; w++) { ts += sred[w]; t2 += sred[8 + w]; }
        float mean = ts * (1.0f / DM);
        float var  = t2 * (1.0f / DM) - mean * mean;
        sred[0] = mean;
        sred[1] = rsqrtf(var + 1e-6f);
    }
    __syncthreads();
    float mean = sred[0], rstd = sred[1];
    float4 g4 = *(const float4*)&gamma[t*4];
    float4 b4 = *(const float4*)&beta[t*4];
    float4 o;
    o.x = (vv.x - mean) * rstd * g4.x + b4.x;
    o.y = (vv.y - mean) * rstd * g4.y + b4.y;
    o.z = (vv.z - mean) * rstd * g4.z + b4.z;
    o.w = (vv.w - mean) * rstd * g4.w + b4.w;
    *(float4*)&y[base] = o;
}

// ---------------- launch ----------------
extern "C" void kernel_launch(void* const* d_in, const int* in_sizes, int n_in,
                              void* d_out, int out_size)
{
    const float* x     = (const float*)d_in[0];
    const float* Wq    = (const float*)d_in[1];
    const float* Wk    = (const float*)d_in[2];
    const float* Wv    = (const float*)d_in[3];
    const float* Wo    = (const float*)d_in[4];
    const float* gamma = (const float*)d_in[5];
    const float* beta  = (const float*)d_in[6];

    float* out      = (float*)d_out;
    float* y_out    = out;
    float* attn_out = out + (size_t)BATCH * SEQ * DM;

    float *xpe, *proj;
    cudaGetSymbolAddress((void**)&xpe,  g_xpe);
    cudaGetSymbolAddress((void**)&proj, g_proj);

    __half *xh, *xl, *qh, *kh, *vth, *ch, *wq, *wk, *wv, *wo;
    cudaGetSymbolAddress((void**)&xh,  g_xh);
    cudaGetSymbolAddress((void**)&xl,  g_xl);
    cudaGetSymbolAddress((void**)&qh,  g_qh);
    cudaGetSymbolAddress((void**)&kh,  g_kh);
    cudaGetSymbolAddress((void**)&vth, g_vth);
    cudaGetSymbolAddress((void**)&ch,  g_ch);
    cudaGetSymbolAddress((void**)&wq,  g_wq);
    cudaGetSymbolAddress((void**)&wk,  g_wk);
    cudaGetSymbolAddress((void**)&wv,  g_wv);
    cudaGetSymbolAddress((void**)&wo,  g_wo);

    const int GEMM_SMEM2 = 2 * 3 * TILE_B;   // 110592
    const int GEMM_SMEM1 = 2 * 2 * TILE_B;   // 73728

    cudaFuncSetAttribute((const void*)gemm_h<2, OUT_H1>,
                         cudaFuncAttributeMaxDynamicSharedMemorySize, GEMM_SMEM2);
    cudaFuncSetAttribute((const void*)gemm_h<1, OUT_VT>,
                         cudaFuncAttributeMaxDynamicSharedMemorySize, GEMM_SMEM1);
    cudaFuncSetAttribute((const void*)gemm_h<1, OUT_F32>,
                         cudaFuncAttributeMaxDynamicSharedMemorySize, GEMM_SMEM1);
    cudaFuncSetAttribute((const void*)attn_mma,
                         cudaFuncAttributeMaxDynamicSharedMemorySize, ATTN_SMEM);

    const int M = BATCH * SEQ;       // 4096
    const int NW4 = DM * DM / 4;     // 262144
    dim3 ggrid(DM / 128, M / 128);   // (8, 32)

    pe_split<<<M, 256>>>(x, xpe, xh, xl);
    h_convert4<<<dim3(NW4 / 256, 4), 256>>>(Wq, Wk, Wv, Wo, wq, wk, wv, wo, NW4);

    gemm_h<2, OUT_H1><<<ggrid, 256, GEMM_SMEM2>>>(xh, xl, wq, nullptr, qh, 0.125f);
    gemm_h<2, OUT_H1><<<ggrid, 256, GEMM_SMEM2>>>(xh, xl, wk, nullptr, kh, 1.0f);
    gemm_h<1, OUT_VT><<<ggrid, 256, GEMM_SMEM1>>>(xh, nullptr, wv, nullptr, vth, 1.0f);

    attn_mma<<<dim3(SEQ / 128, NH, BATCH), 256, ATTN_SMEM>>>(
        qh, kh, vth, attn_out, ch);

    gemm_h<1, OUT_F32><<<ggrid, 256, GEMM_SMEM1>>>(ch, nullptr, wo, proj, nullptr, 1.0f);
    ln_kernel<<<M, 256>>>(proj, xpe, gamma, beta, y_out);
}

// round 8
// speedup vs baseline: 7.3115x; 1.2445x over previous
#include <cuda_runtime.h>
#include <cuda_fp16.h>
#include <math.h>
#include <stdint.h>

#define BATCH 4
#define SEQ   1024
#define DM    1024
#define NH    16
#define DKH   64

// ---------------- scratch (device globals: allocation-free) ----------------
__device__ float g_xpe [BATCH*SEQ*DM];
__device__ float g_proj[BATCH*SEQ*DM];

__device__ __half g_xh[BATCH*SEQ*DM];
__device__ __half g_qh[BATCH*SEQ*DM];
__device__ __half g_kh[BATCH*SEQ*DM];
__device__ __half g_vth[BATCH*SEQ*DM];
__device__ __half g_ch[BATCH*SEQ*DM];
__device__ __half g_wq[DM*DM], g_wk[DM*DM], g_wv[DM*DM], g_wo[DM*DM];

// Q pre-scale: (1/sqrt(dk)) * log2(e), so attention can use raw ex2
#define QSCALE 0.1803368801111204f

// ---------------- PTX helpers (plain sm_103-safe) ----------------
__device__ __forceinline__ uint32_t smem_u32(const void* p) {
    uint32_t a;
    asm("{ .reg .u64 t; cvta.to.shared.u64 t, %1; cvt.u32.u64 %0, t; }" : "=r"(a) : "l"(p));
    return a;
}
__device__ __forceinline__ float fexp2(float x) {
    float y;
    asm("ex2.approx.ftz.f32 %0, %1;" : "=f"(y) : "f"(x));
    return y;
}

#define LDMATRIX_X4(r0,r1,r2,r3,addr) \
    asm volatile("ldmatrix.sync.aligned.m8n8.x4.shared.b16 {%0,%1,%2,%3}, [%4];" \
                 : "=r"(r0),"=r"(r1),"=r"(r2),"=r"(r3) : "r"(addr))

#define MMA_F16(d0,d1,d2,d3,a0,a1,a2,a3,b0,b1) \
    asm volatile("mma.sync.aligned.m16n8k16.row.col.f32.f16.f16.f32 " \
                 "{%0,%1,%2,%3}, {%4,%5,%6,%7}, {%8,%9}, {%0,%1,%2,%3};" \
                 : "+f"(d0),"+f"(d1),"+f"(d2),"+f"(d3) \
                 : "r"(a0),"r"(a1),"r"(a2),"r"(a3),"r"(b0),"r"(b1))

#define CP_ASYNC16(smem, gptr) \
    asm volatile("cp.async.cg.shared.global [%0], [%1], 16;" :: "r"(smem), "l"(gptr))
#define CP_COMMIT() asm volatile("cp.async.commit_group;")
#define CP_WAIT1()  asm volatile("cp.async.wait_group 1;")
#define CP_WAIT0()  asm volatile("cp.async.wait_group 0;")

__device__ __forceinline__ uint32_t pack2h(float x, float y) {
    __half2 h2 = __floats2half2_rn(x, y);
    return *reinterpret_cast<uint32_t*>(&h2);
}

// ---------------- kernel 1: x + PE -> xpe fp32 AND xh fp16 ----------------
__global__ __launch_bounds__(256) void pe_split(const float* __restrict__ x,
                                                float* __restrict__ xpe,
                                                __half* __restrict__ xh)
{
    int row = blockIdx.x;
    int t   = threadIdx.x;
    int s   = row & (SEQ - 1);
    float pos = (float)s;
    const float C = 9.210340371976184f / 1024.0f;
    size_t base = (size_t)row * DM + t * 4;
    float4 xv = *(const float4*)&x[base];
    int d0 = t * 4;
    float div0 = expf(-C * (float)d0);
    float div1 = expf(-C * (float)(d0 + 2));
    float a0 = pos * div0, a1 = pos * div1;
    float4 o;
    o.x = xv.x + sinf(a0);
    o.y = xv.y + cosf(a0);
    o.z = xv.z + sinf(a1);
    o.w = xv.w + cosf(a1);
    *(float4*)&xpe[base] = o;
    *(uint2*)&xh[base] = make_uint2(pack2h(o.x, o.y), pack2h(o.z, o.w));
}

// ---------------- kernel: 4 weight matrices fp32 -> fp16 in one launch ----------------
__global__ __launch_bounds__(256) void h_convert4(const float* __restrict__ s0,
                                                  const float* __restrict__ s1,
                                                  const float* __restrict__ s2,
                                                  const float* __restrict__ s3,
                                                  __half* __restrict__ d0,
                                                  __half* __restrict__ d1,
                                                  __half* __restrict__ d2,
                                                  __half* __restrict__ d3,
                                                  int n4)
{
    int i = blockIdx.x * 256 + threadIdx.x;
    if (i >= n4) return;
    const float* s; __half* d;
    switch (blockIdx.y) {
        case 0: s = s0; d = d0; break;
        case 1: s = s1; d = d1; break;
        case 2: s = s2; d = d2; break;
        default: s = s3; d = d3; break;
    }
    float4 v = ((const float4*)s)[i];
    ((uint2*)d)[i] = make_uint2(pack2h(v.x, v.y), pack2h(v.z, v.w));
}

// ---------------- GEMM framework: 128x128 tile, 1-term fp16, double-buffered ----------------
#define KCHUNK 64
#define NCHV   (DM / KCHUNK)              // 16
#define ROWB   144                        // 128B data + 16B pad
#define TILE_B (128 * ROWB)               // 18432
#define BUF_B  (2 * TILE_B)               // A, B
#define GEMM_SMEM (2 * BUF_B)             // 73728

// Core: compute acc = A[m0:m0+128,:] @ B[n0:n0+128,:]^T
template<typename EPI>
__device__ __forceinline__ void gemm_body(const __half* __restrict__ Ah,
                                          const __half* __restrict__ Bh,
                                          int m0, int n0, uint32_t sb, EPI epi)
{
    int t = threadIdx.x;
    int lane = t & 31, wid = t >> 5;
    int warp_m = (wid & 1) * 64;
    int warp_n = (wid >> 1) * 32;

    float acc[4][4][4];
#pragma unroll
    for (int i = 0; i < 4; i++)
#pragma unroll
        for (int j = 0; j < 4; j++)
#pragma unroll
            for (int r = 0; r < 4; r++) acc[i][j][r] = 0.f;

    auto stage = [&](uint32_t bufb, int koff) {
#pragma unroll
        for (int i = 0; i < 4; i++) {
            int id = t + i * 256;
            int r = id >> 3, c = id & 7;
            uint32_t so = r * ROWB + c * 16;
            CP_ASYNC16(bufb + so,          Ah + (size_t)(m0 + r) * DM + koff + c * 8);
            CP_ASYNC16(bufb + TILE_B + so, Bh + (size_t)(n0 + r) * DM + koff + c * 8);
        }
    };

    stage(sb, 0);
    CP_COMMIT();

    int arow = lane & 15;
    int akb  = (lane >> 4) * 16;
    int brow = (lane & 7) + ((lane >> 4) << 3);
    int bkb  = ((lane >> 3) & 1) * 16;

    for (int ch = 0; ch < NCHV; ch++) {
        int buf = ch & 1;
        uint32_t bufb = sb + buf * BUF_B;

        if (ch + 1 < NCHV) {
            stage(sb + ((ch + 1) & 1) * BUF_B, (ch + 1) * KCHUNK);
            CP_COMMIT();
            CP_WAIT1();
        } else {
            CP_WAIT0();
        }
        __syncthreads();

        uint32_t sAh = bufb;
        uint32_t sBh = bufb + TILE_B;

#pragma unroll
        for (int ks = 0; ks < 4; ks++) {
            int kb = ks * 32;
            uint32_t ah[4][4];
#pragma unroll
            for (int mt = 0; mt < 4; mt++) {
                uint32_t off = (uint32_t)((warp_m + mt * 16 + arow) * ROWB + kb + akb);
                LDMATRIX_X4(ah[mt][0], ah[mt][1], ah[mt][2], ah[mt][3], sAh + off);
            }
#pragma unroll
            for (int np = 0; np < 2; np++) {
                uint32_t boff = (uint32_t)((warp_n + np * 16 + brow) * ROWB + kb + bkb);
                uint32_t bh[4];
                LDMATRIX_X4(bh[0], bh[1], bh[2], bh[3], sBh + boff);
#pragma unroll
                for (int hf = 0; hf < 2; hf++) {
                    int nt = np * 2 + hf;
                    uint32_t b0 = bh[hf*2], b1 = bh[hf*2+1];
#pragma unroll
                    for (int mt = 0; mt < 4; mt++) {
                        float* d = acc[mt][nt];
                        MMA_F16(d[0],d[1],d[2],d[3],
                                ah[mt][0],ah[mt][1],ah[mt][2],ah[mt][3], b0,b1);
                    }
                }
            }
        }
        __syncthreads();
    }

    int g  = lane >> 2;
    int tg = lane & 3;
#pragma unroll
    for (int mt = 0; mt < 4; mt++) {
#pragma unroll
        for (int nt = 0; nt < 4; nt++) {
            int row = m0 + warp_m + mt * 16 + g;
            int col = n0 + warp_n + nt * 8 + tg * 2;
            epi(row, col,       acc[mt][nt][0], acc[mt][nt][1]);
            epi(row + 8, col,   acc[mt][nt][2], acc[mt][nt][3]);
        }
    }
}

// ---------------- merged QKV GEMM ----------------
// grid (3*DM/128, M/128); column block selects weight + epilogue mode.
__global__ void __launch_bounds__(256, 2) gemm_qkv(const __half* __restrict__ xh,
                                                   const __half* __restrict__ wq,
                                                   const __half* __restrict__ wk,
                                                   const __half* __restrict__ wv,
                                                   __half* __restrict__ qh,
                                                   __half* __restrict__ kh,
                                                   __half* __restrict__ vth)
{
    extern __shared__ char smem[];
    uint32_t sb = smem_u32(smem);
    int n0g = blockIdx.x * 128;
    int wsel = n0g >> 10;
    int n0 = n0g & (DM - 1);
    int m0 = blockIdx.y * 128;
    const __half* Bh = (wsel == 0) ? wq : (wsel == 1) ? wk : wv;

    if (wsel == 0) {
        gemm_body(xh, Bh, m0, n0, sb, [&](int row, int col, float c0, float c1) {
            *(uint32_t*)&qh[(size_t)row * DM + col] = pack2h(c0 * QSCALE, c1 * QSCALE);
        });
    } else if (wsel == 1) {
        gemm_body(xh, Bh, m0, n0, sb, [&](int row, int col, float c0, float c1) {
            *(uint32_t*)&kh[(size_t)row * DM + col] = pack2h(c0, c1);
        });
    } else {
        gemm_body(xh, Bh, m0, n0, sb, [&](int row, int col, float c0, float c1) {
            int b_ = row >> 10, s_ = row & (SEQ - 1);
            int h_ = col >> 6,  dh = col & 63;
            size_t vbase = (((size_t)(b_ * NH + h_)) * DKH + dh) * SEQ + s_;
            vth[vbase]       = __float2half(c0);
            vth[vbase + SEQ] = __float2half(c1);
        });
    }
}

// ---------------- Wo GEMM (fp32 out) ----------------
__global__ void __launch_bounds__(256, 2) gemm_wo(const __half* __restrict__ ch,
                                                  const __half* __restrict__ wo,
                                                  float* __restrict__ proj)
{
    extern __shared__ char smem[];
    uint32_t sb = smem_u32(smem);
    int m0 = blockIdx.y * 128, n0 = blockIdx.x * 128;
    gemm_body(ch, wo, m0, n0, sb, [&](int row, int col, float c0, float c1) {
        *(float2*)&proj[(size_t)row * DM + col] = make_float2(c0, c1);
    });
}

// ---------------- kernel 3: fp16 mma flash attention, two-pass ----------------
// grid (SEQ/128, NH, BATCH), 256 threads (8 warps x 16 q-rows).
// Q pre-scaled by log2(e)/8 -> p = 2^s via ex2.approx.
#define AROWB 144
#define AMAT  (64 * AROWB)        // 9216
#define QMAT  (128 * AROWB)       // 18432
#define ABUF  (2 * AMAT)          // Kh + Vth per buffer
#define AKV   (sb + QMAT)
#define ATTN_SMEM (QMAT + 2 * ABUF)   // 55296

__global__ void __launch_bounds__(256, 2) attn_mma(
    const __half* __restrict__ qh,
    const __half* __restrict__ kh, const __half* __restrict__ vth,
    float* __restrict__ attn_out,
    __half* __restrict__ cth)
{
    extern __shared__ char smem[];
    uint32_t sb = smem_u32(smem);
    int t = threadIdx.x, lane = t & 31, wid = t >> 5;
    int q0 = blockIdx.x * 128;
    int h  = blockIdx.y, b = blockIdx.z;
    int g  = lane >> 2, tg = lane & 3;

    size_t qoff = ((size_t)b * SEQ + q0) * DM + h * DKH;
    size_t koff = ((size_t)b * SEQ) * DM + h * DKH;
    size_t voff = ((size_t)(b * NH + h)) * DKH * SEQ;

#pragma unroll
    for (int i = 0; i < 4; i++) {
        int id = t + i * 256;
        int r = id >> 3, c = id & 7;
        CP_ASYNC16(sb + r * AROWB + c * 16, qh + qoff + (size_t)r * DM + c * 8);
    }
    CP_COMMIT(); CP_WAIT0();
    __syncthreads();

    uint32_t aqh[4][4];
    {
        int arow = lane & 15, akb = (lane >> 4) * 16;
        uint32_t qs = sb + (wid * 16 + arow) * AROWB + akb;
#pragma unroll
        for (int ks = 0; ks < 4; ks++)
            LDMATRIX_X4(aqh[ks][0], aqh[ks][1], aqh[ks][2], aqh[ks][3], qs + ks * 32);
    }
    __syncthreads();

    int brow = (lane & 7) + ((lane >> 4) << 3);
    int bkb  = ((lane >> 3) & 1) * 16;

    auto load_k = [&](int kt, int buf) {
        uint32_t bb = AKV + buf * ABUF;
#pragma unroll
        for (int i = 0; i < 2; i++) {
            int id = t + i * 256;
            int r = id >> 3, c = id & 7;
            CP_ASYNC16(bb + r * AROWB + c * 16,
                       kh + koff + (size_t)(kt * 64 + r) * DM + c * 8);
        }
    };
    auto load_v = [&](int kt, int buf) {
        uint32_t bb = AKV + buf * ABUF + AMAT;
#pragma unroll
        for (int i = 0; i < 2; i++) {
            int id = t + i * 256;
            int r = id >> 3, c = id & 7;
            CP_ASYNC16(bb + r * AROWB + c * 16,
                       vth + voff + (size_t)r * SEQ + kt * 64 + c * 8);
        }
    };

    // ================= pass 1: rowsums =================
    float l0 = 0.f, l1 = 0.f;
    load_k(0, 0); CP_COMMIT();
    for (int kt = 0; kt < SEQ / 64; kt++) {
        int buf = kt & 1;
        if (kt + 1 < SEQ / 64) { load_k(kt + 1, buf ^ 1); CP_COMMIT(); CP_WAIT1(); }
        else CP_WAIT0();
        __syncthreads();
        uint32_t sKh = AKV + buf * ABUF;
#pragma unroll
        for (int np = 0; np < 4; np++) {
            float s_acc[2][4] = {{0.f,0.f,0.f,0.f},{0.f,0.f,0.f,0.f}};
#pragma unroll
            for (int ks = 0; ks < 4; ks++) {
                uint32_t off = (uint32_t)((np * 16 + brow) * AROWB + ks * 32 + bkb);
                uint32_t bh[4];
                LDMATRIX_X4(bh[0], bh[1], bh[2], bh[3], sKh + off);
#pragma unroll
                for (int hf = 0; hf < 2; hf++) {
                    float* d = s_acc[hf];
                    MMA_F16(d[0],d[1],d[2],d[3], aqh[ks][0],aqh[ks][1],aqh[ks][2],aqh[ks][3], bh[hf*2],bh[hf*2+1]);
                }
            }
#pragma unroll
            for (int hf = 0; hf < 2; hf++) {
                l0 += fexp2(s_acc[hf][0]) + fexp2(s_acc[hf][1]);
                l1 += fexp2(s_acc[hf][2]) + fexp2(s_acc[hf][3]);
            }
        }
        __syncthreads();
    }
    l0 += __shfl_xor_sync(0xffffffffu, l0, 1);
    l0 += __shfl_xor_sync(0xffffffffu, l0, 2);
    l1 += __shfl_xor_sync(0xffffffffu, l1, 1);
    l1 += __shfl_xor_sync(0xffffffffu, l1, 2);
    float inv0 = 1.f / l0, inv1 = 1.f / l1;

    // ================= pass 2: attn + PV =================
    float o_acc[8][4];
#pragma unroll
    for (int nt = 0; nt < 8; nt++)
#pragma unroll
        for (int r = 0; r < 4; r++) o_acc[nt][r] = 0.f;

    size_t abase = (((size_t)(b * NH + h)) * SEQ + q0 + wid * 16) * SEQ;

    load_k(0, 0); load_v(0, 0); CP_COMMIT();
    for (int kt = 0; kt < SEQ / 64; kt++) {
        int buf = kt & 1;
        if (kt + 1 < SEQ / 64) { load_k(kt + 1, buf ^ 1); load_v(kt + 1, buf ^ 1); CP_COMMIT(); CP_WAIT1(); }
        else CP_WAIT0();
        __syncthreads();
        uint32_t sKh = AKV + buf * ABUF;
        uint32_t sVh = sKh + AMAT;

        uint32_t ph[4][4];
#pragma unroll
        for (int np = 0; np < 4; np++) {
            float s_acc[2][4] = {{0.f,0.f,0.f,0.f},{0.f,0.f,0.f,0.f}};
#pragma unroll
            for (int ks = 0; ks < 4; ks++) {
                uint32_t off = (uint32_t)((np * 16 + brow) * AROWB + ks * 32 + bkb);
                uint32_t bh[4];
                LDMATRIX_X4(bh[0], bh[1], bh[2], bh[3], sKh + off);
#pragma unroll
                for (int hf = 0; hf < 2; hf++) {
                    float* d = s_acc[hf];
                    MMA_F16(d[0],d[1],d[2],d[3], aqh[ks][0],aqh[ks][1],aqh[ks][2],aqh[ks][3], bh[hf*2],bh[hf*2+1]);
                }
            }
#pragma unroll
            for (int hf = 0; hf < 2; hf++) {
                float p0 = fexp2(s_acc[hf][0]) * inv0;
                float p1 = fexp2(s_acc[hf][1]) * inv0;
                float p2 = fexp2(s_acc[hf][2]) * inv1;
                float p3 = fexp2(s_acc[hf][3]) * inv1;
                int col = kt * 64 + (np * 2 + hf) * 8 + tg * 2;
                *(float2*)&attn_out[abase + (size_t)g * SEQ + col]       = make_float2(p0, p1);
                *(float2*)&attn_out[abase + (size_t)(g + 8) * SEQ + col] = make_float2(p2, p3);
                ph[np][hf * 2 + 0] = pack2h(p0, p1);
                ph[np][hf * 2 + 1] = pack2h(p2, p3);
            }
        }

#pragma unroll
        for (int np = 0; np < 4; np++)
#pragma unroll
            for (int ks = 0; ks < 4; ks++) {
                uint32_t off = (uint32_t)((np * 16 + brow) * AROWB + ks * 32 + bkb);
                uint32_t bh[4];
                LDMATRIX_X4(bh[0], bh[1], bh[2], bh[3], sVh + off);
#pragma unroll
                for (int hf = 0; hf < 2; hf++) {
                    float* d = o_acc[np * 2 + hf];
                    MMA_F16(d[0],d[1],d[2],d[3], ph[ks][0],ph[ks][1],ph[ks][2],ph[ks][3], bh[hf*2],bh[hf*2+1]);
                }
            }
        __syncthreads();
    }

    size_t cbase = ((size_t)b * SEQ + q0 + wid * 16) * DM + h * DKH;
#pragma unroll
    for (int nt = 0; nt < 8; nt++) {
        int col = nt * 8 + tg * 2;
        *(uint32_t*)&cth[cbase + (size_t)g * DM + col]       = pack2h(o_acc[nt][0], o_acc[nt][1]);
        *(uint32_t*)&cth[cbase + (size_t)(g + 8) * DM + col] = pack2h(o_acc[nt][2], o_acc[nt][3]);
    }
}

// ---------------- kernel 4: residual + LayerNorm ----------------
__global__ __launch_bounds__(256) void ln_kernel(const float* __restrict__ proj,
                                                 const float* __restrict__ resid,
                                                 const float* __restrict__ gamma,
                                                 const float* __restrict__ beta,
                                                 float* __restrict__ y)
{
    __shared__ float sred[16];
    int row = blockIdx.x;
    int t   = threadIdx.x;
    size_t base = (size_t)row * DM + t * 4;
    float4 pv = *(const float4*)&proj[base];
    float4 rv = *(const float4*)&resid[base];
    float4 vv = make_float4(pv.x+rv.x, pv.y+rv.y, pv.z+rv.z, pv.w+rv.w);
    float s  = vv.x + vv.y + vv.z + vv.w;
    float s2 = vv.x*vv.x + vv.y*vv.y + vv.z*vv.z + vv.w*vv.w;
#pragma unroll
    for (int off = 16; off; off >>= 1) {
        s  += __shfl_xor_sync(0xffffffffu, s,  off);
        s2 += __shfl_xor_sync(0xffffffffu, s2, off);
    }
    int warp = t >> 5, lane = t & 31;
    if (lane == 0) { sred[warp] = s; sred[8 + warp] = s2; }
    __syncthreads();
    if (t == 0) {
        float ts = 0.f, t2 = 0.f;
#pragma unroll
        for (int w = 0; w < 8; w++) { ts += sred[w]; t2 += sred[8 + w]; }
        float mean = ts * (1.0f / DM);
        float var  = t2 * (1.0f / DM) - mean * mean;
        sred[0] = mean;
        sred[1] = rsqrtf(var + 1e-6f);
    }
    __syncthreads();
    float mean = sred[0], rstd = sred[1];
    float4 g4 = *(const float4*)&gamma[t*4];
    float4 b4 = *(const float4*)&beta[t*4];
    float4 o;
    o.x = (vv.x - mean) * rstd * g4.x + b4.x;
    o.y = (vv.y - mean) * rstd * g4.y + b4.y;
    o.z = (vv.z - mean) * rstd * g4.z + b4.z;
    o.w = (vv.w - mean) * rstd * g4.w + b4.w;
    *(float4*)&y[base] = o;
}

// ---------------- launch ----------------
extern "C" void kernel_launch(void* const* d_in, const int* in_sizes, int n_in,
                              void* d_out, int out_size)
{
    const float* x     = (const float*)d_in[0];
    const float* Wq    = (const float*)d_in[1];
    const float* Wk    = (const float*)d_in[2];
    const float* Wv    = (const float*)d_in[3];
    const float* Wo    = (const float*)d_in[4];
    const float* gamma = (const float*)d_in[5];
    const float* beta  = (const float*)d_in[6];

    float* out      = (float*)d_out;
    float* y_out    = out;
    float* attn_out = out + (size_t)BATCH * SEQ * DM;

    float *xpe, *proj;
    cudaGetSymbolAddress((void**)&xpe,  g_xpe);
    cudaGetSymbolAddress((void**)&proj, g_proj);

    __half *xh, *qh, *kh, *vth, *ch, *wq, *wk, *wv, *wo;
    cudaGetSymbolAddress((void**)&xh,  g_xh);
    cudaGetSymbolAddress((void**)&qh,  g_qh);
    cudaGetSymbolAddress((void**)&kh,  g_kh);
    cudaGetSymbolAddress((void**)&vth, g_vth);
    cudaGetSymbolAddress((void**)&ch,  g_ch);
    cudaGetSymbolAddress((void**)&wq,  g_wq);
    cudaGetSymbolAddress((void**)&wk,  g_wk);
    cudaGetSymbolAddress((void**)&wv,  g_wv);
    cudaGetSymbolAddress((void**)&wo,  g_wo);

    cudaFuncSetAttribute((const void*)gemm_qkv,
                         cudaFuncAttributeMaxDynamicSharedMemorySize, GEMM_SMEM);
    cudaFuncSetAttribute((const void*)gemm_wo,
                         cudaFuncAttributeMaxDynamicSharedMemorySize, GEMM_SMEM);
    cudaFuncSetAttribute((const void*)attn_mma,
                         cudaFuncAttributeMaxDynamicSharedMemorySize, ATTN_SMEM);

    const int M = BATCH * SEQ;       // 4096
    const int NW4 = DM * DM / 4;     // 262144

    pe_split<<<M, 256>>>(x, xpe, xh);
    h_convert4<<<dim3(NW4 / 256, 4), 256>>>(Wq, Wk, Wv, Wo, wq, wk, wv, wo, NW4);

    gemm_qkv<<<dim3(3 * DM / 128, M / 128), 256, GEMM_SMEM>>>(xh, wq, wk, wv, qh, kh, vth);

    attn_mma<<<dim3(SEQ / 128, NH, BATCH), 256, ATTN_SMEM>>>(
        qh, kh, vth, attn_out, ch);

    gemm_wo<<<dim3(DM / 128, M / 128), 256, GEMM_SMEM>>>(ch, wo, proj);
    ln_kernel<<<M, 256>>>(proj, xpe, gamma, beta, y_out);
}

// round 10
// speedup vs baseline: 7.6021x; 1.0398x over previous
#include <cuda_runtime.h>
#include <cuda_fp16.h>
#include <math.h>
#include <stdint.h>

#define BATCH 4
#define SEQ   1024
#define DM    1024
#define NH    16
#define DKH   64

// ---------------- scratch (device globals: allocation-free) ----------------
__device__ float g_xpe [BATCH*SEQ*DM];
__device__ float g_proj[BATCH*SEQ*DM];

__device__ __half g_xh[BATCH*SEQ*DM];
__device__ __half g_qh[BATCH*SEQ*DM];
__device__ __half g_kh[BATCH*SEQ*DM];
__device__ __half g_vth[BATCH*SEQ*DM];
__device__ __half g_ch[BATCH*SEQ*DM];
__device__ __half g_wq[DM*DM], g_wk[DM*DM], g_wv[DM*DM], g_wo[DM*DM];

// Q pre-scale: (1/sqrt(dk)) * log2(e), so attention can use raw ex2
#define QSCALE 0.1803368801111204f

// ---------------- PTX helpers (plain sm_103-safe) ----------------
__device__ __forceinline__ uint32_t smem_u32(const void* p) {
    uint32_t a;
    asm("{ .reg .u64 t; cvta.to.shared.u64 t, %1; cvt.u32.u64 %0, t; }" : "=r"(a) : "l"(p));
    return a;
}
__device__ __forceinline__ float fexp2(float x) {
    float y;
    asm("ex2.approx.ftz.f32 %0, %1;" : "=f"(y) : "f"(x));
    return y;
}

#define LDMATRIX_X4(r0,r1,r2,r3,addr) \
    asm volatile("ldmatrix.sync.aligned.m8n8.x4.shared.b16 {%0,%1,%2,%3}, [%4];" \
                 : "=r"(r0),"=r"(r1),"=r"(r2),"=r"(r3) : "r"(addr))

#define MMA_F16(d0,d1,d2,d3,a0,a1,a2,a3,b0,b1) \
    asm volatile("mma.sync.aligned.m16n8k16.row.col.f32.f16.f16.f32 " \
                 "{%0,%1,%2,%3}, {%4,%5,%6,%7}, {%8,%9}, {%0,%1,%2,%3};" \
                 : "+f"(d0),"+f"(d1),"+f"(d2),"+f"(d3) \
                 : "r"(a0),"r"(a1),"r"(a2),"r"(a3),"r"(b0),"r"(b1))

#define CP_ASYNC16(smem, gptr) \
    asm volatile("cp.async.cg.shared.global [%0], [%1], 16;" :: "r"(smem), "l"(gptr))
#define CP_COMMIT() asm volatile("cp.async.commit_group;")
#define CP_WAIT1()  asm volatile("cp.async.wait_group 1;")
#define CP_WAIT0()  asm volatile("cp.async.wait_group 0;")

__device__ __forceinline__ uint32_t pack2h(float x, float y) {
    __half2 h2 = __floats2half2_rn(x, y);
    return *reinterpret_cast<uint32_t*>(&h2);
}

// ---------------- kernel 1: x + PE -> xpe fp32 AND xh fp16 ----------------
__global__ __launch_bounds__(256) void pe_split(const float* __restrict__ x,
                                                float* __restrict__ xpe,
                                                __half* __restrict__ xh)
{
    int row = blockIdx.x;
    int t   = threadIdx.x;
    int s   = row & (SEQ - 1);
    float pos = (float)s;
    const float C = 9.210340371976184f / 1024.0f;
    size_t base = (size_t)row * DM + t * 4;
    float4 xv = *(const float4*)&x[base];
    int d0 = t * 4;
    float div0 = expf(-C * (float)d0);
    float div1 = expf(-C * (float)(d0 + 2));
    float a0 = pos * div0, a1 = pos * div1;
    float4 o;
    o.x = xv.x + sinf(a0);
    o.y = xv.y + cosf(a0);
    o.z = xv.z + sinf(a1);
    o.w = xv.w + cosf(a1);
    *(float4*)&xpe[base] = o;
    *(uint2*)&xh[base] = make_uint2(pack2h(o.x, o.y), pack2h(o.z, o.w));
}

// ---------------- kernel: 4 weight matrices fp32 -> fp16 in one launch ----------------
__global__ __launch_bounds__(256) void h_convert4(const float* __restrict__ s0,
                                                  const float* __restrict__ s1,
                                                  const float* __restrict__ s2,
                                                  const float* __restrict__ s3,
                                                  __half* __restrict__ d0,
                                                  __half* __restrict__ d1,
                                                  __half* __restrict__ d2,
                                                  __half* __restrict__ d3,
                                                  int n4)
{
    int i = blockIdx.x * 256 + threadIdx.x;
    if (i >= n4) return;
    const float* s; __half* d;
    switch (blockIdx.y) {
        case 0: s = s0; d = d0; break;
        case 1: s = s1; d = d1; break;
        case 2: s = s2; d = d2; break;
        default: s = s3; d = d3; break;
    }
    float4 v = ((const float4*)s)[i];
    ((uint2*)d)[i] = make_uint2(pack2h(v.x, v.y), pack2h(v.z, v.w));
}

// ---------------- GEMM framework: 128x128 tile, 1-term fp16, double-buffered ----------------
#define KCHUNK 64
#define NCHV   (DM / KCHUNK)              // 16
#define ROWB   144                        // 128B data + 16B pad
#define TILE_B (128 * ROWB)               // 18432
#define BUF_B  (2 * TILE_B)               // A, B
#define GEMM_SMEM (2 * BUF_B)             // 73728

template<typename EPI>
__device__ __forceinline__ void gemm_body(const __half* __restrict__ Ah,
                                          const __half* __restrict__ Bh,
                                          int m0, int n0, uint32_t sb, EPI epi)
{
    int t = threadIdx.x;
    int lane = t & 31, wid = t >> 5;
    int warp_m = (wid & 1) * 64;
    int warp_n = (wid >> 1) * 32;

    float acc[4][4][4];
#pragma unroll
    for (int i = 0; i < 4; i++)
#pragma unroll
        for (int j = 0; j < 4; j++)
#pragma unroll
            for (int r = 0; r < 4; r++) acc[i][j][r] = 0.f;

    auto stage = [&](uint32_t bufb, int koff) {
#pragma unroll
        for (int i = 0; i < 4; i++) {
            int id = t + i * 256;
            int r = id >> 3, c = id & 7;
            uint32_t so = r * ROWB + c * 16;
            CP_ASYNC16(bufb + so,          Ah + (size_t)(m0 + r) * DM + koff + c * 8);
            CP_ASYNC16(bufb + TILE_B + so, Bh + (size_t)(n0 + r) * DM + koff + c * 8);
        }
    };

    stage(sb, 0);
    CP_COMMIT();

    int arow = lane & 15;
    int akb  = (lane >> 4) * 16;
    int brow = (lane & 7) + ((lane >> 4) << 3);
    int bkb  = ((lane >> 3) & 1) * 16;

    for (int ch = 0; ch < NCHV; ch++) {
        int buf = ch & 1;
        uint32_t bufb = sb + buf * BUF_B;

        if (ch + 1 < NCHV) {
            stage(sb + ((ch + 1) & 1) * BUF_B, (ch + 1) * KCHUNK);
            CP_COMMIT();
            CP_WAIT1();
        } else {
            CP_WAIT0();
        }
        __syncthreads();

        uint32_t sAh = bufb;
        uint32_t sBh = bufb + TILE_B;

#pragma unroll
        for (int ks = 0; ks < 4; ks++) {
            int kb = ks * 32;
            uint32_t ah[4][4];
#pragma unroll
            for (int mt = 0; mt < 4; mt++) {
                uint32_t off = (uint32_t)((warp_m + mt * 16 + arow) * ROWB + kb + akb);
                LDMATRIX_X4(ah[mt][0], ah[mt][1], ah[mt][2], ah[mt][3], sAh + off);
            }
#pragma unroll
            for (int np = 0; np < 2; np++) {
                uint32_t boff = (uint32_t)((warp_n + np * 16 + brow) * ROWB + kb + bkb);
                uint32_t bh[4];
                LDMATRIX_X4(bh[0], bh[1], bh[2], bh[3], sBh + boff);
#pragma unroll
                for (int hf = 0; hf < 2; hf++) {
                    int nt = np * 2 + hf;
                    uint32_t b0 = bh[hf*2], b1 = bh[hf*2+1];
#pragma unroll
                    for (int mt = 0; mt < 4; mt++) {
                        float* d = acc[mt][nt];
                        MMA_F16(d[0],d[1],d[2],d[3],
                                ah[mt][0],ah[mt][1],ah[mt][2],ah[mt][3], b0,b1);
                    }
                }
            }
        }
        __syncthreads();
    }

    int g  = lane >> 2;
    int tg = lane & 3;
#pragma unroll
    for (int mt = 0; mt < 4; mt++) {
#pragma unroll
        for (int nt = 0; nt < 4; nt++) {
            int row = m0 + warp_m + mt * 16 + g;
            int col = n0 + warp_n + nt * 8 + tg * 2;
            epi(row, col,       acc[mt][nt][0], acc[mt][nt][1]);
            epi(row + 8, col,   acc[mt][nt][2], acc[mt][nt][3]);
        }
    }
}

// ---------------- merged QKV GEMM ----------------
__global__ void __launch_bounds__(256, 2) gemm_qkv(const __half* __restrict__ xh,
                                                   const __half* __restrict__ wq,
                                                   const __half* __restrict__ wk,
                                                   const __half* __restrict__ wv,
                                                   __half* __restrict__ qh,
                                                   __half* __restrict__ kh,
                                                   __half* __restrict__ vth)
{
    extern __shared__ char smem[];
    uint32_t sb = smem_u32(smem);
    int n0g = blockIdx.x * 128;
    int wsel = n0g >> 10;
    int n0 = n0g & (DM - 1);
    int m0 = blockIdx.y * 128;
    const __half* Bh = (wsel == 0) ? wq : (wsel == 1) ? wk : wv;

    if (wsel == 0) {
        gemm_body(xh, Bh, m0, n0, sb, [&](int row, int col, float c0, float c1) {
            *(uint32_t*)&qh[(size_t)row * DM + col] = pack2h(c0 * QSCALE, c1 * QSCALE);
        });
    } else if (wsel == 1) {
        gemm_body(xh, Bh, m0, n0, sb, [&](int row, int col, float c0, float c1) {
            *(uint32_t*)&kh[(size_t)row * DM + col] = pack2h(c0, c1);
        });
    } else {
        gemm_body(xh, Bh, m0, n0, sb, [&](int row, int col, float c0, float c1) {
            int b_ = row >> 10, s_ = row & (SEQ - 1);
            int h_ = col >> 6,  dh = col & 63;
            size_t vbase = (((size_t)(b_ * NH + h_)) * DKH + dh) * SEQ + s_;
            vth[vbase]       = __float2half(c0);
            vth[vbase + SEQ] = __float2half(c1);
        });
    }
}

// ---------------- Wo GEMM (fp32 out) ----------------
__global__ void __launch_bounds__(256, 2) gemm_wo(const __half* __restrict__ ch,
                                                  const __half* __restrict__ wo,
                                                  float* __restrict__ proj)
{
    extern __shared__ char smem[];
    uint32_t sb = smem_u32(smem);
    int m0 = blockIdx.y * 128, n0 = blockIdx.x * 128;
    gemm_body(ch, wo, m0, n0, sb, [&](int row, int col, float c0, float c1) {
        *(float2*)&proj[(size_t)row * DM + col] = make_float2(c0, c1);
    });
}

// ---------------- kernel 3: fp16 mma flash attention, two-pass ----------------
// grid (SEQ/128, NH, BATCH), 128 threads (4 warps x 32 q-rows each).
// Warp M-tile = 32 => each K/V B-fragment feeds 4 MMAs (2 mh x 2 hf):
// half the ldmatrix traffic per MMA vs M=16. 3 CTAs/SM.
#define AROWB 144
#define AMAT  (64 * AROWB)        // 9216
#define QMAT  (128 * AROWB)       // 18432
#define ABUF  (2 * AMAT)          // Kh + Vth per buffer
#define AKV   (sb + QMAT)
#define ATTN_SMEM (QMAT + 2 * ABUF)   // 55296

__global__ void __launch_bounds__(128, 3) attn_mma(
    const __half* __restrict__ qh,
    const __half* __restrict__ kh, const __half* __restrict__ vth,
    float* __restrict__ attn_out,
    __half* __restrict__ cth)
{
    extern __shared__ char smem[];
    uint32_t sb = smem_u32(smem);
    int t = threadIdx.x, lane = t & 31, wid = t >> 5;   // 4 warps
    int q0 = blockIdx.x * 128;
    int h  = blockIdx.y, b = blockIdx.z;
    int g  = lane >> 2, tg = lane & 3;

    size_t qoff = ((size_t)b * SEQ + q0) * DM + h * DKH;
    size_t koff = ((size_t)b * SEQ) * DM + h * DKH;
    size_t voff = ((size_t)(b * NH + h)) * DKH * SEQ;

    // ---- stage Q (128 x 64 fp16) ----
#pragma unroll
    for (int i = 0; i < 8; i++) {
        int id = t + i * 128;
        int r = id >> 3, c = id & 7;
        CP_ASYNC16(sb + r * AROWB + c * 16, qh + qoff + (size_t)r * DM + c * 8);
    }
    CP_COMMIT(); CP_WAIT0();
    __syncthreads();

    // Q fragments: 2 m-halves (mh) x 4 ksteps, warp rows = wid*32 + mh*16 + ...
    uint32_t aqh[2][4][4];
    {
        int arow = lane & 15, akb = (lane >> 4) * 16;
#pragma unroll
        for (int mh = 0; mh < 2; mh++) {
            uint32_t qs = sb + (wid * 32 + mh * 16 + arow) * AROWB + akb;
#pragma unroll
            for (int ks = 0; ks < 4; ks++)
                LDMATRIX_X4(aqh[mh][ks][0], aqh[mh][ks][1], aqh[mh][ks][2], aqh[mh][ks][3],
                            qs + ks * 32);
        }
    }
    __syncthreads();

    int brow = (lane & 7) + ((lane >> 4) << 3);
    int bkb  = ((lane >> 3) & 1) * 16;

    auto load_k = [&](int kt, int buf) {
        uint32_t bb = AKV + buf * ABUF;
#pragma unroll
        for (int i = 0; i < 4; i++) {
            int id = t + i * 128;
            int r = id >> 3, c = id & 7;
            CP_ASYNC16(bb + r * AROWB + c * 16,
                       kh + koff + (size_t)(kt * 64 + r) * DM + c * 8);
        }
    };
    auto load_v = [&](int kt, int buf) {
        uint32_t bb = AKV + buf * ABUF + AMAT;
#pragma unroll
        for (int i = 0; i < 4; i++) {
            int id = t + i * 128;
            int r = id >> 3, c = id & 7;
            CP_ASYNC16(bb + r * AROWB + c * 16,
                       vth + voff + (size_t)r * SEQ + kt * 64 + c * 8);
        }
    };

    // ================= pass 1: rowsums =================
    float lsum[2][2] = {{0.f, 0.f}, {0.f, 0.f}};   // [mh][row g / g+8]
    load_k(0, 0); CP_COMMIT();
    for (int kt = 0; kt < SEQ / 64; kt++) {
        int buf = kt & 1;
        if (kt + 1 < SEQ / 64) { load_k(kt + 1, buf ^ 1); CP_COMMIT(); CP_WAIT1(); }
        else CP_WAIT0();
        __syncthreads();
        uint32_t sKh = AKV + buf * ABUF;
#pragma unroll
        for (int np = 0; np < 4; np++) {
            float s_acc[2][2][4];
#pragma unroll
            for (int mh = 0; mh < 2; mh++)
#pragma unroll
                for (int hf = 0; hf < 2; hf++)
#pragma unroll
                    for (int r = 0; r < 4; r++) s_acc[mh][hf][r] = 0.f;
#pragma unroll
            for (int ks = 0; ks < 4; ks++) {
                uint32_t off = (uint32_t)((np * 16 + brow) * AROWB + ks * 32 + bkb);
                uint32_t bh[4];
                LDMATRIX_X4(bh[0], bh[1], bh[2], bh[3], sKh + off);
#pragma unroll
                for (int mh = 0; mh < 2; mh++) {
#pragma unroll
                    for (int hf = 0; hf < 2; hf++) {
                        float* d = s_acc[mh][hf];
                        MMA_F16(d[0],d[1],d[2],d[3],
                                aqh[mh][ks][0],aqh[mh][ks][1],aqh[mh][ks][2],aqh[mh][ks][3],
                                bh[hf*2],bh[hf*2+1]);
                    }
                }
            }
#pragma unroll
            for (int mh = 0; mh < 2; mh++)
#pragma unroll
                for (int hf = 0; hf < 2; hf++) {
                    lsum[mh][0] += fexp2(s_acc[mh][hf][0]) + fexp2(s_acc[mh][hf][1]);
                    lsum[mh][1] += fexp2(s_acc[mh][hf][2]) + fexp2(s_acc[mh][hf][3]);
                }
        }
        __syncthreads();
    }
    float inv[2][2];
#pragma unroll
    for (int mh = 0; mh < 2; mh++)
#pragma unroll
        for (int j = 0; j < 2; j++) {
            float l = lsum[mh][j];
            l += __shfl_xor_sync(0xffffffffu, l, 1);
            l += __shfl_xor_sync(0xffffffffu, l, 2);
            inv[mh][j] = 1.f / l;
        }

    // ================= pass 2: attn + PV =================
    float o_acc[2][8][4];
#pragma unroll
    for (int mh = 0; mh < 2; mh++)
#pragma unroll
        for (int nt = 0; nt < 8; nt++)
#pragma unroll
            for (int r = 0; r < 4; r++) o_acc[mh][nt][r] = 0.f;

    size_t abase = (((size_t)(b * NH + h)) * SEQ + q0 + wid * 32) * SEQ;

    load_k(0, 0); load_v(0, 0); CP_COMMIT();
    for (int kt = 0; kt < SEQ / 64; kt++) {
        int buf = kt & 1;
        if (kt + 1 < SEQ / 64) { load_k(kt + 1, buf ^ 1); load_v(kt + 1, buf ^ 1); CP_COMMIT(); CP_WAIT1(); }
        else CP_WAIT0();
        __syncthreads();
        uint32_t sKh = AKV + buf * ABUF;
        uint32_t sVh = sKh + AMAT;

        uint32_t ph[2][4][4];
#pragma unroll
        for (int np = 0; np < 4; np++) {
            float s_acc[2][2][4];
#pragma unroll
            for (int mh = 0; mh < 2; mh++)
#pragma unroll
                for (int hf = 0; hf < 2; hf++)
#pragma unroll
                    for (int r = 0; r < 4; r++) s_acc[mh][hf][r] = 0.f;
#pragma unroll
            for (int ks = 0; ks < 4; ks++) {
                uint32_t off = (uint32_t)((np * 16 + brow) * AROWB + ks * 32 + bkb);
                uint32_t bh[4];
                LDMATRIX_X4(bh[0], bh[1], bh[2], bh[3], sKh + off);
#pragma unroll
                for (int mh = 0; mh < 2; mh++) {
#pragma unroll
                    for (int hf = 0; hf < 2; hf++) {
                        float* d = s_acc[mh][hf];
                        MMA_F16(d[0],d[1],d[2],d[3],
                                aqh[mh][ks][0],aqh[mh][ks][1],aqh[mh][ks][2],aqh[mh][ks][3],
                                bh[hf*2],bh[hf*2+1]);
                    }
                }
            }
#pragma unroll
            for (int mh = 0; mh < 2; mh++)
#pragma unroll
                for (int hf = 0; hf < 2; hf++) {
                    float p0 = fexp2(s_acc[mh][hf][0]) * inv[mh][0];
                    float p1 = fexp2(s_acc[mh][hf][1]) * inv[mh][0];
                    float p2 = fexp2(s_acc[mh][hf][2]) * inv[mh][1];
                    float p3 = fexp2(s_acc[mh][hf][3]) * inv[mh][1];
                    int col = kt * 64 + (np * 2 + hf) * 8 + tg * 2;
                    size_t rbase = abase + (size_t)(mh * 16 + g) * SEQ;
                    *(float2*)&attn_out[rbase + col]           = make_float2(p0, p1);
                    *(float2*)&attn_out[rbase + 8 * SEQ + col] = make_float2(p2, p3);
                    ph[mh][np][hf * 2 + 0] = pack2h(p0, p1);
                    ph[mh][np][hf * 2 + 1] = pack2h(p2, p3);
                }
        }

        // PV: A = P fragments (ks = key-steps), B = Vt [d][key]
#pragma unroll
        for (int np = 0; np < 4; np++)
#pragma unroll
            for (int ks = 0; ks < 4; ks++) {
                uint32_t off = (uint32_t)((np * 16 + brow) * AROWB + ks * 32 + bkb);
                uint32_t bh[4];
                LDMATRIX_X4(bh[0], bh[1], bh[2], bh[3], sVh + off);
#pragma unroll
                for (int mh = 0; mh < 2; mh++) {
#pragma unroll
                    for (int hf = 0; hf < 2; hf++) {
                        float* d = o_acc[mh][np * 2 + hf];
                        MMA_F16(d[0],d[1],d[2],d[3],
                                ph[mh][ks][0],ph[mh][ks][1],ph[mh][ks][2],ph[mh][ks][3],
                                bh[hf*2],bh[hf*2+1]);
                    }
                }
            }
        __syncthreads();
    }

    // write ctx as fp16 (hi only)
    size_t cbase = ((size_t)b * SEQ + q0 + wid * 32) * DM + h * DKH;
#pragma unroll
    for (int mh = 0; mh < 2; mh++)
#pragma unroll
        for (int nt = 0; nt < 8; nt++) {
            int col = nt * 8 + tg * 2;
            size_t rbase = cbase + (size_t)(mh * 16 + g) * DM;
            *(uint32_t*)&cth[rbase + col]          = pack2h(o_acc[mh][nt][0], o_acc[mh][nt][1]);
            *(uint32_t*)&cth[rbase + 8 * DM + col] = pack2h(o_acc[mh][nt][2], o_acc[mh][nt][3]);
        }
}

// ---------------- kernel 4: residual + LayerNorm ----------------
__global__ __launch_bounds__(256) void ln_kernel(const float* __restrict__ proj,
                                                 const float* __restrict__ resid,
                                                 const float* __restrict__ gamma,
                                                 const float* __restrict__ beta,
                                                 float* __restrict__ y)
{
    __shared__ float sred[16];
    int row = blockIdx.x;
    int t   = threadIdx.x;
    size_t base = (size_t)row * DM + t * 4;
    float4 pv = *(const float4*)&proj[base];
    float4 rv = *(const float4*)&resid[base];
    float4 vv = make_float4(pv.x+rv.x, pv.y+rv.y, pv.z+rv.z, pv.w+rv.w);
    float s  = vv.x + vv.y + vv.z + vv.w;
    float s2 = vv.x*vv.x + vv.y*vv.y + vv.z*vv.z + vv.w*vv.w;
#pragma unroll
    for (int off = 16; off; off >>= 1) {
        s  += __shfl_xor_sync(0xffffffffu, s,  off);
        s2 += __shfl_xor_sync(0xffffffffu, s2, off);
    }
    int warp = t >> 5, lane = t & 31;
    if (lane == 0) { sred[warp] = s; sred[8 + warp] = s2; }
    __syncthreads();
    if (t == 0) {
        float ts = 0.f, t2 = 0.f;
#pragma unroll
        for (int w = 0; w < 8; w++) { ts += sred[w]; t2 += sred[8 + w]; }
        float mean = ts * (1.0f / DM);
        float var  = t2 * (1.0f / DM) - mean * mean;
        sred[0] = mean;
        sred[1] = rsqrtf(var + 1e-6f);
    }
    __syncthreads();
    float mean = sred[0], rstd = sred[1];
    float4 g4 = *(const float4*)&gamma[t*4];
    float4 b4 = *(const float4*)&beta[t*4];
    float4 o;
    o.x = (vv.x - mean) * rstd * g4.x + b4.x;
    o.y = (vv.y - mean) * rstd * g4.y + b4.y;
    o.z = (vv.z - mean) * rstd * g4.z + b4.z;
    o.w = (vv.w - mean) * rstd * g4.w + b4.w;
    *(float4*)&y[base] = o;
}

// ---------------- launch ----------------
extern "C" void kernel_launch(void* const* d_in, const int* in_sizes, int n_in,
                              void* d_out, int out_size)
{
    const float* x     = (const float*)d_in[0];
    const float* Wq    = (const float*)d_in[1];
    const float* Wk    = (const float*)d_in[2];
    const float* Wv    = (const float*)d_in[3];
    const float* Wo    = (const float*)d_in[4];
    const float* gamma = (const float*)d_in[5];
    const float* beta  = (const float*)d_in[6];

    float* out      = (float*)d_out;
    float* y_out    = out;
    float* attn_out = out + (size_t)BATCH * SEQ * DM;

    float *xpe, *proj;
    cudaGetSymbolAddress((void**)&xpe,  g_xpe);
    cudaGetSymbolAddress((void**)&proj, g_proj);

    __half *xh, *qh, *kh, *vth, *ch, *wq, *wk, *wv, *wo;
    cudaGetSymbolAddress((void**)&xh,  g_xh);
    cudaGetSymbolAddress((void**)&qh,  g_qh);
    cudaGetSymbolAddress((void**)&kh,  g_kh);
    cudaGetSymbolAddress((void**)&vth, g_vth);
    cudaGetSymbolAddress((void**)&ch,  g_ch);
    cudaGetSymbolAddress((void**)&wq,  g_wq);
    cudaGetSymbolAddress((void**)&wk,  g_wk);
    cudaGetSymbolAddress((void**)&wv,  g_wv);
    cudaGetSymbolAddress((void**)&wo,  g_wo);

    cudaFuncSetAttribute((const void*)gemm_qkv,
                         cudaFuncAttributeMaxDynamicSharedMemorySize, GEMM_SMEM);
    cudaFuncSetAttribute((const void*)gemm_wo,
                         cudaFuncAttributeMaxDynamicSharedMemorySize, GEMM_SMEM);
    cudaFuncSetAttribute((const void*)attn_mma,
                         cudaFuncAttributeMaxDynamicSharedMemorySize, ATTN_SMEM);

    const int M = BATCH * SEQ;       // 4096
    const int NW4 = DM * DM / 4;     // 262144

    pe_split<<<M, 256>>>(x, xpe, xh);
    h_convert4<<<dim3(NW4 / 256, 4), 256>>>(Wq, Wk, Wv, Wo, wq, wk, wv, wo, NW4);

    gemm_qkv<<<dim3(3 * DM / 128, M / 128), 256, GEMM_SMEM>>>(xh, wq, wk, wv, qh, kh, vth);

    attn_mma<<<dim3(SEQ / 128, NH, BATCH), 128, ATTN_SMEM>>>(
        qh, kh, vth, attn_out, ch);

    gemm_wo<<<dim3(DM / 128, M / 128), 256, GEMM_SMEM>>>(ch, wo, proj);
    ln_kernel<<<M, 256>>>(proj, xpe, gamma, beta, y_out);
}